// round 3
// baseline (speedup 1.0000x reference)
#include <cuda_runtime.h>
#include <math.h>

// ---------------- problem constants ----------------
#define BB   2048
#define FF   5
#define NNB  64          // neighbors per node
#define KK   32          // top-k
#define DD   256         // emb dim
#define DMX  512         // DM
#define GSEL 2048        // selected gate width (4 * 512)
#define MCM  (2*BB + 2*FF)   // 4106 catmean rows
#define MX   (BB + FF)       // 2053 encoder rows

// ---------------- scratch (static device globals; no allocation) ----------------
__device__ float g_catmean[(size_t)MCM * 512];
__device__ float g_x     [(size_t)MX * 512];      // query_n / supp_n stacked
__device__ float g_h1    [(size_t)MX * 1024];     // p1 output
__device__ float g_o     [(size_t)MX * 512];      // p2 output (pre-LN)
__device__ float g_enc   [(size_t)MX * 512];      // LN output: query_g rows 0..2047, support enc 2048..2052
__device__ float g_sg    [512];
__device__ float g_sgn   [512];
__device__ float g_Wih   [(size_t)GSEL * 512];
__device__ float g_Whh   [(size_t)GSEL * 512];
__device__ float g_bsel  [GSEL];
__device__ float g_Svec  [GSEL];
__device__ float g_G0    [(size_t)BB * GSEL];
__device__ float g_gates [(size_t)BB * GSEL];
__device__ float g_c     [(size_t)BB * 512];
__device__ float g_hcur  [(size_t)BB * 512];

// ---------------- kernel 1: weight selection prep ----------------
// selected gate row r -> original row (r/512)*1024 + r%512
__global__ void k_prep(const float* __restrict__ w_ih, const float* __restrict__ w_hh,
                       const float* __restrict__ b_ih, const float* __restrict__ b_hh,
                       float* __restrict__ Wih, float* __restrict__ Whh, float* __restrict__ bsel)
{
    int i = blockIdx.x * blockDim.x + threadIdx.x;   // exactly GSEL*512 threads
    if (i >= GSEL * 512) return;
    int r = i >> 9, k = i & 511;
    int orig = ((r >> 9) << 10) + (r & 511);
    Wih[i] = w_ih[(long)orig * 512 + k];
    Whh[i] = w_hh[(long)orig * 1024 + k];          // left half cols 0..511
    if (k == 0) bsel[r] = b_ih[orig] + b_hh[orig];
}

// ---------------- kernel 2: neighbor encode (sim + exact top-k + mean) ----------------
__global__ void __launch_bounds__(256) k_neighbor(
    const int* __restrict__ query, const int* __restrict__ support,
    const int* __restrict__ qlc, const int* __restrict__ qrc,
    const int* __restrict__ slc, const int* __restrict__ src_,
    const float* __restrict__ emb, float* __restrict__ catmean)
{
    __shared__ int   s_conn[2 * NNB];
    __shared__ float s_center[DD];
    __shared__ float s_sim[NNB];
    __shared__ int   s_sel[NNB];
    __shared__ float s_red[9];

    int tid = threadIdx.x;
    int blk = blockIdx.x;
    const int* conn; int id;
    if (blk < 2 * BB) {
        int b = blk >> 1, s = blk & 1;
        conn = (s ? qrc : qlc) + (long)b * (2 * NNB);
        id = query[2 * b + s];
    } else {
        int t = blk - 2 * BB; int f = t >> 1, s = t & 1;
        conn = (s ? src_ : slc) + (long)f * (2 * NNB);
        id = support[2 * f + s];
    }
    if (tid < 2 * NNB) s_conn[tid] = conn[tid];

    float cv = emb[(long)id * DD + tid];
    s_center[tid] = cv;
    float cs = cv * cv;
    #pragma unroll
    for (int o = 16; o; o >>= 1) cs += __shfl_down_sync(0xffffffffu, cs, o);
    if ((tid & 31) == 0) s_red[tid >> 5] = cs;
    __syncthreads();
    if (tid == 0) { float t = 0.f; for (int i = 0; i < 8; i++) t += s_red[i]; s_red[8] = sqrtf(t); }
    __syncthreads();
    float cnorm = s_red[8];

    // cosine sims: warp per neighbor
    int w = tid >> 5, l = tid & 31;
    for (int n = w; n < NNB; n += 8) {
        const float* e = emb + (long)s_conn[2 * n + 1] * DD;
        float d = 0.f, q = 0.f;
        #pragma unroll
        for (int i = l; i < DD; i += 32) { float v = e[i]; d += v * s_center[i]; q += v * v; }
        #pragma unroll
        for (int o = 16; o; o >>= 1) {
            d += __shfl_down_sync(0xffffffffu, d, o);
            q += __shfl_down_sync(0xffffffffu, q, o);
        }
        if (l == 0) s_sim[n] = d / fmaxf(cnorm * sqrtf(q), 1e-8f);
    }
    __syncthreads();

    // exact top-K with jax.lax.top_k tie-break (lower index wins on ties)
    if (tid < NNB) {
        float sn = s_sim[tid]; int rank = 0;
        #pragma unroll
        for (int m = 0; m < NNB; m++) {
            float sm = s_sim[m];
            rank += (sm > sn) || (sm == sn && m < tid);
        }
        s_sel[tid] = (rank < KK);
    }
    __syncthreads();

    // mean of selected rel / ent embeddings
    float ra = 0.f, ea = 0.f;
    for (int n = 0; n < NNB; n++) {
        if (s_sel[n]) {
            ra += emb[(long)s_conn[2 * n]     * DD + tid];
            ea += emb[(long)s_conn[2 * n + 1] * DD + tid];
        }
    }
    catmean[(long)blk * 512 + tid]      = ra * (1.0f / KK);   // rel first (concat order)
    catmean[(long)blk * 512 + DD + tid] = ea * (1.0f / KK);
}

// ---------------- kernel 3: generic fp32 GEMM  C = act(A @ W^T + b1 + b2 + R) ----------------
// A: (M,K) row-major, W: (N,K) row-major, C/R: (M,N). N % 128 == 0, K % 16 == 0. M guarded.
__global__ void __launch_bounds__(256) k_gemm(
    const float* __restrict__ A, const float* __restrict__ W,
    const float* __restrict__ b1, const float* __restrict__ b2,
    const float* __restrict__ R, float* __restrict__ C,
    int M, int N, int K, int act)
{
    __shared__ float As[16 * 132];
    __shared__ float Bs[16 * 132];
    int tid = threadIdx.x;
    int bm0 = blockIdx.y * 128, bn0 = blockIdx.x * 128;
    int tx = tid & 15, ty = tid >> 4;
    int lr = tid >> 2, lc = (tid & 3) << 2;

    float acc[8][8];
    #pragma unroll
    for (int i = 0; i < 8; i++)
        #pragma unroll
        for (int j = 0; j < 8; j++) acc[i][j] = 0.f;

    for (int k0 = 0; k0 < K; k0 += 16) {
        #pragma unroll
        for (int h2 = 0; h2 < 2; h2++) {
            int r = bm0 + lr + h2 * 64;
            float4 v = (r < M) ? *(const float4*)&A[(long)r * K + k0 + lc]
                               : make_float4(0.f, 0.f, 0.f, 0.f);
            int mo = lr + h2 * 64;
            As[(lc + 0) * 132 + mo] = v.x;
            As[(lc + 1) * 132 + mo] = v.y;
            As[(lc + 2) * 132 + mo] = v.z;
            As[(lc + 3) * 132 + mo] = v.w;
        }
        #pragma unroll
        for (int h2 = 0; h2 < 2; h2++) {
            int n = bn0 + lr + h2 * 64;
            float4 v = *(const float4*)&W[(long)n * K + k0 + lc];
            int no = lr + h2 * 64;
            Bs[(lc + 0) * 132 + no] = v.x;
            Bs[(lc + 1) * 132 + no] = v.y;
            Bs[(lc + 2) * 132 + no] = v.z;
            Bs[(lc + 3) * 132 + no] = v.w;
        }
        __syncthreads();
        #pragma unroll
        for (int k = 0; k < 16; k++) {
            float4 a0 = *(const float4*)&As[k * 132 + ty * 8];
            float4 a1 = *(const float4*)&As[k * 132 + ty * 8 + 4];
            float4 c0 = *(const float4*)&Bs[k * 132 + tx * 8];
            float4 c1 = *(const float4*)&Bs[k * 132 + tx * 8 + 4];
            float av[8] = {a0.x, a0.y, a0.z, a0.w, a1.x, a1.y, a1.z, a1.w};
            float bv[8] = {c0.x, c0.y, c0.z, c0.w, c1.x, c1.y, c1.z, c1.w};
            #pragma unroll
            for (int i = 0; i < 8; i++)
                #pragma unroll
                for (int j = 0; j < 8; j++) acc[i][j] += av[i] * bv[j];
        }
        __syncthreads();
    }

    #pragma unroll
    for (int i = 0; i < 8; i++) {
        int row = bm0 + ty * 8 + i;
        if (row >= M) continue;
        #pragma unroll
        for (int j = 0; j < 8; j++) {
            int col = bn0 + tx * 8 + j;
            float v = acc[i][j];
            if (b1) v += b1[col];
            if (b2) v += b2[col];
            if (R)  v += R[(long)row * N + col];
            if (act == 1)      v = fmaxf(v, 0.f);
            else if (act == 2) v = tanhf(v);
            C[(long)row * N + col] = v;
        }
    }
}

// ---------------- kernel 4: layernorm (per row of 512) ----------------
__global__ void k_layernorm(const float* __restrict__ X, const float* __restrict__ g,
                            const float* __restrict__ b, float* __restrict__ Y)
{
    __shared__ float rs[8], rq[8];
    int r = blockIdx.x, t = threadIdx.x;  // 256 threads
    const float* x = X + (long)r * 512;
    float v0 = x[t], v1 = x[t + 256];
    float s = v0 + v1, q = v0 * v0 + v1 * v1;
    #pragma unroll
    for (int o = 16; o; o >>= 1) {
        s += __shfl_down_sync(0xffffffffu, s, o);
        q += __shfl_down_sync(0xffffffffu, q, o);
    }
    if ((t & 31) == 0) { rs[t >> 5] = s; rq[t >> 5] = q; }
    __syncthreads();
    if (t == 0) {
        float ts = 0.f, tq = 0.f;
        for (int i = 0; i < 8; i++) { ts += rs[i]; tq += rq[i]; }
        rs[0] = ts; rq[0] = tq;
    }
    __syncthreads();
    float m   = rs[0] * (1.f / 512.f);
    float var = rq[0] * (1.f / 512.f) - m * m;
    float inv = 1.0f / sqrtf(var + 1e-5f);
    Y[(long)r * 512 + t]       = (v0 - m) * inv * g[t]       + b[t];
    Y[(long)r * 512 + t + 256] = (v1 - m) * inv * g[t + 256] + b[t + 256];
}

// ---------------- kernel 5: support_g = mean of encoded support rows ----------------
__global__ void k_sgmean(const float* __restrict__ enc, float* __restrict__ sg)
{
    int t = threadIdx.x;  // 512
    float a = 0.f;
    for (int f = 0; f < FF; f++) a += enc[(long)(BB + f) * 512 + t];
    sg[t] = a * (1.0f / FF);
}

// ---------------- kernel 6: S[r] = dot(w_hh[orig_r, 512:1024], support_g) ----------------
__global__ void k_svec(const float* __restrict__ w_hh, const float* __restrict__ sg,
                       float* __restrict__ S)
{
    int gw = (blockIdx.x * blockDim.x + threadIdx.x) >> 5;
    int l  = threadIdx.x & 31;
    if (gw >= GSEL) return;
    int orig = ((gw >> 9) << 10) + (gw & 511);
    const float* row = w_hh + (long)orig * 1024 + 512;
    float a = 0.f;
    for (int j = l; j < 512; j += 32) a += row[j] * sg[j];
    #pragma unroll
    for (int o = 16; o; o >>= 1) a += __shfl_down_sync(0xffffffffu, a, o);
    if (l == 0) S[gw] = a;
}

// ---------------- kernel 7: LSTM elementwise ----------------
__global__ void k_lstm(const float* __restrict__ gates, const float* __restrict__ qg,
                       float* __restrict__ c, float* __restrict__ h, int first)
{
    int i = blockIdx.x * blockDim.x + threadIdx.x;
    if (i >= BB * 512) return;
    int b = i >> 9, j = i & 511;
    const float* gr = gates + (long)b * GSEL;
    float gi = gr[j], gf = gr[j + 512], gg = gr[j + 1024], go = gr[j + 1536];
    float cp = first ? 0.f : c[i];
    float cn = (1.f / (1.f + expf(-gf))) * cp + (1.f / (1.f + expf(-gi))) * tanhf(gg);
    c[i] = cn;
    h[i] = qg[i] + (1.f / (1.f + expf(-go))) * tanhf(cn);
}

// ---------------- kernel 8: normalize support_g ----------------
__global__ void k_sgnorm(const float* __restrict__ sg, float* __restrict__ sgn)
{
    __shared__ float red[16];
    int t = threadIdx.x;  // 512
    float v = sg[t], q = v * v;
    #pragma unroll
    for (int o = 16; o; o >>= 1) q += __shfl_down_sync(0xffffffffu, q, o);
    if ((t & 31) == 0) red[t >> 5] = q;
    __syncthreads();
    if (t == 0) { float s = 0.f; for (int i = 0; i < 16; i++) s += red[i]; red[0] = sqrtf(s); }
    __syncthreads();
    sgn[t] = v / fmaxf(red[0], 1e-12f);
}

// ---------------- kernel 9: out[b] = dot(h_b, sgn) / max(||h_b||, 1e-12) ----------------
__global__ void k_final(const float* __restrict__ h, const float* __restrict__ sgn,
                        float* __restrict__ out)
{
    int gw = (blockIdx.x * blockDim.x + threadIdx.x) >> 5;
    int l  = threadIdx.x & 31;
    if (gw >= BB) return;
    const float* hr = h + (long)gw * 512;
    float d = 0.f, q = 0.f;
    for (int j = l; j < 512; j += 32) { float v = hr[j]; d += v * sgn[j]; q += v * v; }
    #pragma unroll
    for (int o = 16; o; o >>= 1) {
        d += __shfl_down_sync(0xffffffffu, d, o);
        q += __shfl_down_sync(0xffffffffu, q, o);
    }
    if (l == 0) out[gw] = d / fmaxf(sqrtf(q), 1e-12f);
}

// ---------------- launch ----------------
extern "C" void kernel_launch(void* const* d_in, const int* in_sizes, int n_in,
                              void* d_out, int out_size)
{
    const int*   query   = (const int*)  d_in[0];
    const int*   support = (const int*)  d_in[1];
    const int*   qlc     = (const int*)  d_in[2];
    const int*   qrc     = (const int*)  d_in[4];
    const int*   slc     = (const int*)  d_in[6];
    const int*   src_    = (const int*)  d_in[8];
    const float* emb     = (const float*)d_in[10];
    const float* gcn_w   = (const float*)d_in[11];
    const float* gcn_wb  = (const float*)d_in[12];
    const float* gcn_b   = (const float*)d_in[13];
    const float* p1_w    = (const float*)d_in[14];
    const float* p1_b    = (const float*)d_in[15];
    const float* p2_w    = (const float*)d_in[16];
    const float* p2_b    = (const float*)d_in[17];
    const float* ln_g    = (const float*)d_in[18];
    const float* ln_b    = (const float*)d_in[19];
    const float* w_ih    = (const float*)d_in[20];
    const float* w_hh    = (const float*)d_in[21];
    const float* b_ih    = (const float*)d_in[22];
    const float* b_hh    = (const float*)d_in[23];
    float* out = (float*)d_out;

    float *catmean, *x, *h1, *o, *enc, *sg, *sgn, *Wih, *Whh, *bsel, *Svec, *G0, *gates, *c, *hcur;
    cudaGetSymbolAddress((void**)&catmean, g_catmean);
    cudaGetSymbolAddress((void**)&x,       g_x);
    cudaGetSymbolAddress((void**)&h1,      g_h1);
    cudaGetSymbolAddress((void**)&o,       g_o);
    cudaGetSymbolAddress((void**)&enc,     g_enc);
    cudaGetSymbolAddress((void**)&sg,      g_sg);
    cudaGetSymbolAddress((void**)&sgn,     g_sgn);
    cudaGetSymbolAddress((void**)&Wih,     g_Wih);
    cudaGetSymbolAddress((void**)&Whh,     g_Whh);
    cudaGetSymbolAddress((void**)&bsel,    g_bsel);
    cudaGetSymbolAddress((void**)&Svec,    g_Svec);
    cudaGetSymbolAddress((void**)&G0,      g_G0);
    cudaGetSymbolAddress((void**)&gates,   g_gates);
    cudaGetSymbolAddress((void**)&c,       g_c);
    cudaGetSymbolAddress((void**)&hcur,    g_hcur);

    // 1. selected-gate weight prep (deterministic, cheap)
    k_prep<<<(GSEL * 512) / 512, 512>>>(w_ih, w_hh, b_ih, b_hh, Wih, Whh, bsel);

    // 2. neighbor encoder gather + top-k + mean  -> catmean (4106 x 512)
    k_neighbor<<<MCM, 256>>>(query, support, qlc, qrc, slc, src_, emb, catmean);

    // 3. GCN: tanh(catmean @ gcn_w^T + wb + b)  -> writes directly as x (2053 x 512)
    k_gemm<<<dim3(2, 33), 256>>>(catmean, gcn_w, gcn_wb, gcn_b, nullptr, x, MCM, 256, 512, 2);

    // 4. support encoder MLP: h1 = relu(x @ p1^T + b1);  o = h1 @ p2^T + b2 + x;  LN -> enc
    k_gemm<<<dim3(8, 17), 256>>>(x,  p1_w, p1_b, nullptr, nullptr, h1, MX, 1024, 512, 1);
    k_gemm<<<dim3(4, 17), 256>>>(h1, p2_w, p2_b, nullptr, x,       o,  MX, 512, 1024, 0);
    k_layernorm<<<MX, 256>>>(o, ln_g, ln_b, enc);
    k_sgmean<<<1, 512>>>(enc, sg);

    // 5. G0 = query_g @ Wih_sel^T + (b_ih + b_hh)_sel   (2048 x 2048)
    k_gemm<<<dim3(16, 16), 256>>>(enc, Wih, bsel, nullptr, nullptr, G0, BB, GSEL, 512, 0);
    k_svec<<<(GSEL * 32) / 256, 256>>>(w_hh, sg, Svec);

    // 6. LSTM steps (step 0: h_r = 0 -> gates = G0)
    k_lstm<<<(BB * 512) / 256, 256>>>(G0, enc, c, hcur, 1);
    for (int s = 1; s < 4; s++) {
        k_gemm<<<dim3(16, 16), 256>>>(hcur, Whh, Svec, nullptr, G0, gates, BB, GSEL, 512, 0);
        k_lstm<<<(BB * 512) / 256, 256>>>(gates, enc, c, hcur, 0);
    }

    // 7. cosine output
    k_sgnorm<<<1, 512>>>(sg, sgn);
    k_final<<<(BB * 32) / 256, 256>>>(hcur, sgn, out);
}

// round 10
// speedup vs baseline: 1.1511x; 1.1511x over previous
#include <cuda_runtime.h>
#include <cstdint>
#include <math.h>

// ---------------- problem constants ----------------
#define BB   2048
#define FF   5
#define NNB  64          // neighbors per node
#define KK   32          // top-k
#define DD   256         // emb dim
#define GSEL 2048        // selected gate width (4 * 512)
#define MCM  (2*BB + 2*FF)   // 4106 catmean rows
#define MX   (BB + FF)       // 2053 encoder rows

// ---------------- scratch (static device globals; no allocation) ----------------
__device__ float g_catmean[(size_t)MCM * 512];
__device__ float g_x     [(size_t)MX * 512];
__device__ float g_h1    [(size_t)MX * 1024];
__device__ float g_o     [(size_t)MX * 512];
__device__ float g_enc   [(size_t)MX * 512];
__device__ float g_sg    [512];
__device__ float g_sgn   [512];
__device__ float g_Wih   [(size_t)GSEL * 512];
__device__ float g_Whh   [(size_t)GSEL * 512];
__device__ float g_bsel  [GSEL];
__device__ float g_Svec  [GSEL];
__device__ float g_G0    [(size_t)BB * GSEL];
__device__ float g_gates [(size_t)BB * GSEL];
__device__ float g_c     [(size_t)BB * 512];
__device__ float g_hcur  [(size_t)BB * 512];

__device__ __forceinline__ uint32_t f2tf32(float x) {
    uint32_t r;
    asm("cvt.rna.tf32.f32 %0, %1;" : "=r"(r) : "f"(x));
    return r;
}

// ---------------- kernel 1: weight selection prep ----------------
__global__ void k_prep(const float* __restrict__ w_ih, const float* __restrict__ w_hh,
                       const float* __restrict__ b_ih, const float* __restrict__ b_hh,
                       float* __restrict__ Wih, float* __restrict__ Whh, float* __restrict__ bsel)
{
    int i = blockIdx.x * blockDim.x + threadIdx.x;
    if (i >= GSEL * 512) return;
    int r = i >> 9, k = i & 511;
    int orig = ((r >> 9) << 10) + (r & 511);
    Wih[i] = w_ih[(long)orig * 512 + k];
    Whh[i] = w_hh[(long)orig * 1024 + k];
    if (k == 0) bsel[r] = b_ih[orig] + b_hh[orig];
}

// ---------------- kernel 2: neighbor encode (sim + exact top-k + mean) ----------------
__global__ void __launch_bounds__(256) k_neighbor(
    const int* __restrict__ query, const int* __restrict__ support,
    const int* __restrict__ qlc, const int* __restrict__ qrc,
    const int* __restrict__ slc, const int* __restrict__ src_,
    const float* __restrict__ emb, float* __restrict__ catmean)
{
    __shared__ int   s_conn[2 * NNB];
    __shared__ float s_center[DD];
    __shared__ float s_sim[NNB];
    __shared__ int   s_sel[NNB];
    __shared__ float s_red[9];

    int tid = threadIdx.x;
    int blk = blockIdx.x;
    const int* conn; int id;
    if (blk < 2 * BB) {
        int b = blk >> 1, s = blk & 1;
        conn = (s ? qrc : qlc) + (long)b * (2 * NNB);
        id = query[2 * b + s];
    } else {
        int t = blk - 2 * BB; int f = t >> 1, s = t & 1;
        conn = (s ? src_ : slc) + (long)f * (2 * NNB);
        id = support[2 * f + s];
    }
    if (tid < 2 * NNB) s_conn[tid] = conn[tid];

    float cv = emb[(long)id * DD + tid];
    s_center[tid] = cv;
    float cs = cv * cv;
    #pragma unroll
    for (int o = 16; o; o >>= 1) cs += __shfl_down_sync(0xffffffffu, cs, o);
    if ((tid & 31) == 0) s_red[tid >> 5] = cs;
    __syncthreads();
    if (tid == 0) { float t = 0.f; for (int i = 0; i < 8; i++) t += s_red[i]; s_red[8] = sqrtf(t); }
    __syncthreads();
    float cnorm = s_red[8];

    int w = tid >> 5, l = tid & 31;
    for (int n = w; n < NNB; n += 8) {
        const float* e = emb + (long)s_conn[2 * n + 1] * DD;
        float d = 0.f, q = 0.f;
        #pragma unroll
        for (int i = l; i < DD; i += 32) { float v = e[i]; d += v * s_center[i]; q += v * v; }
        #pragma unroll
        for (int o = 16; o; o >>= 1) {
            d += __shfl_down_sync(0xffffffffu, d, o);
            q += __shfl_down_sync(0xffffffffu, q, o);
        }
        if (l == 0) s_sim[n] = d / fmaxf(cnorm * sqrtf(q), 1e-8f);
    }
    __syncthreads();

    if (tid < NNB) {
        float sn = s_sim[tid]; int rank = 0;
        #pragma unroll
        for (int m = 0; m < NNB; m++) {
            float sm = s_sim[m];
            rank += (sm > sn) || (sm == sn && m < tid);
        }
        s_sel[tid] = (rank < KK);
    }
    __syncthreads();

    float ra = 0.f, ea = 0.f;
    for (int n = 0; n < NNB; n++) {
        if (s_sel[n]) {
            ra += emb[(long)s_conn[2 * n]     * DD + tid];
            ea += emb[(long)s_conn[2 * n + 1] * DD + tid];
        }
    }
    catmean[(long)blk * 512 + tid]      = ra * (1.0f / KK);
    catmean[(long)blk * 512 + DD + tid] = ea * (1.0f / KK);
}

// ---------------- tf32 mma.sync GEMM: C = act(A @ W^T + b1 + b2 + R) ----------------
// A:(M,K) row-major, W:(N,K) row-major. N%128==0, K%16==0, M guarded.
// CTA tile 128x128, BK=16, 8 warps (2x4), warp tile 64x32, m16n8k8 fragments.
#define SPAD 20   // smem row stride in floats (16 + 4 pad; keeps float4 alignment)

__global__ void __launch_bounds__(256, 2) k_gemm_mma(
    const float* __restrict__ A, const float* __restrict__ W,
    const float* __restrict__ b1, const float* __restrict__ b2,
    const float* __restrict__ R, float* __restrict__ C,
    int M, int N, int K, int act)
{
    __shared__ float As[128 * SPAD];
    __shared__ float Bs[128 * SPAD];

    const int tid = threadIdx.x;
    const int wid = tid >> 5, lane = tid & 31;
    const int bn0 = blockIdx.x * 128, bm0 = blockIdx.y * 128;
    const int wm0 = (wid >> 2) * 64;        // warp m offset (0 or 64)
    const int wn0 = (wid & 3) * 32;         // warp n offset (0,32,64,96)
    const int lg = lane >> 2;               // lane group 0..7
    const int lk = lane & 3;                // k-within-4

    // global load assignment: each thread loads 2 consecutive float4 of one row
    const int ldrow = tid >> 1;             // 0..127
    const int ldcol = (tid & 1) * 8;        // 0 or 8

    float acc[4][4][4];
    #pragma unroll
    for (int mf = 0; mf < 4; mf++)
        #pragma unroll
        for (int nf = 0; nf < 4; nf++)
            #pragma unroll
            for (int j = 0; j < 4; j++) acc[mf][nf][j] = 0.f;

    float4 pa0, pa1, pb0, pb1;
    // prefetch chunk 0
    {
        int gr = bm0 + ldrow;
        if (gr < M) {
            pa0 = *(const float4*)(A + (long)gr * K + ldcol);
            pa1 = *(const float4*)(A + (long)gr * K + ldcol + 4);
        } else { pa0 = make_float4(0,0,0,0); pa1 = pa0; }
        pb0 = *(const float4*)(W + (long)(bn0 + ldrow) * K + ldcol);
        pb1 = *(const float4*)(W + (long)(bn0 + ldrow) * K + ldcol + 4);
    }

    const int chunks = K >> 4;
    for (int kc = 0; kc < chunks; kc++) {
        // store prefetched chunk to smem with tf32 conversion
        {
            float* a = As + ldrow * SPAD + ldcol;
            a[0] = __uint_as_float(f2tf32(pa0.x)); a[1] = __uint_as_float(f2tf32(pa0.y));
            a[2] = __uint_as_float(f2tf32(pa0.z)); a[3] = __uint_as_float(f2tf32(pa0.w));
            a[4] = __uint_as_float(f2tf32(pa1.x)); a[5] = __uint_as_float(f2tf32(pa1.y));
            a[6] = __uint_as_float(f2tf32(pa1.z)); a[7] = __uint_as_float(f2tf32(pa1.w));
            float* b = Bs + ldrow * SPAD + ldcol;
            b[0] = __uint_as_float(f2tf32(pb0.x)); b[1] = __uint_as_float(f2tf32(pb0.y));
            b[2] = __uint_as_float(f2tf32(pb0.z)); b[3] = __uint_as_float(f2tf32(pb0.w));
            b[4] = __uint_as_float(f2tf32(pb1.x)); b[5] = __uint_as_float(f2tf32(pb1.y));
            b[6] = __uint_as_float(f2tf32(pb1.z)); b[7] = __uint_as_float(f2tf32(pb1.w));
        }
        __syncthreads();

        // prefetch next chunk (issues LDGs early; resolves during compute)
        if (kc + 1 < chunks) {
            const long kb = (long)((kc + 1) << 4);
            int gr = bm0 + ldrow;
            if (gr < M) {
                pa0 = *(const float4*)(A + (long)gr * K + kb + ldcol);
                pa1 = *(const float4*)(A + (long)gr * K + kb + ldcol + 4);
            } else { pa0 = make_float4(0,0,0,0); pa1 = pa0; }
            pb0 = *(const float4*)(W + (long)(bn0 + ldrow) * K + kb + ldcol);
            pb1 = *(const float4*)(W + (long)(bn0 + ldrow) * K + kb + ldcol + 4);
        }

        // compute 2 k8-steps
        #pragma unroll
        for (int ks = 0; ks < 2; ks++) {
            const int k0 = ks * 8;
            uint32_t af[4][4];
            #pragma unroll
            for (int mf = 0; mf < 4; mf++) {
                int r0 = wm0 + mf * 16 + lg;
                af[mf][0] = __float_as_uint(As[(r0)     * SPAD + k0 + lk]);
                af[mf][1] = __float_as_uint(As[(r0 + 8) * SPAD + k0 + lk]);
                af[mf][2] = __float_as_uint(As[(r0)     * SPAD + k0 + lk + 4]);
                af[mf][3] = __float_as_uint(As[(r0 + 8) * SPAD + k0 + lk + 4]);
            }
            uint32_t bf[4][2];
            #pragma unroll
            for (int nf = 0; nf < 4; nf++) {
                int n = wn0 + nf * 8 + lg;
                bf[nf][0] = __float_as_uint(Bs[n * SPAD + k0 + lk]);
                bf[nf][1] = __float_as_uint(Bs[n * SPAD + k0 + lk + 4]);
            }
            #pragma unroll
            for (int mf = 0; mf < 4; mf++)
                #pragma unroll
                for (int nf = 0; nf < 4; nf++) {
                    asm volatile(
                        "mma.sync.aligned.m16n8k8.row.col.f32.tf32.tf32.f32 "
                        "{%0,%1,%2,%3}, {%4,%5,%6,%7}, {%8,%9}, {%0,%1,%2,%3};"
                        : "+f"(acc[mf][nf][0]), "+f"(acc[mf][nf][1]),
                          "+f"(acc[mf][nf][2]), "+f"(acc[mf][nf][3])
                        : "r"(af[mf][0]), "r"(af[mf][1]), "r"(af[mf][2]), "r"(af[mf][3]),
                          "r"(bf[nf][0]), "r"(bf[nf][1]));
                }
        }
        __syncthreads();
    }

    // epilogue: c0:(row, col) c1:(row, col+1) c2:(row+8, col) c3:(row+8, col+1)
    // row = lg (+8), col = lk*2
    #pragma unroll
    for (int mf = 0; mf < 4; mf++) {
        #pragma unroll
        for (int half = 0; half < 2; half++) {
            int row = bm0 + wm0 + mf * 16 + lg + half * 8;
            if (row >= M) continue;
            #pragma unroll
            for (int nf = 0; nf < 4; nf++) {
                int col = bn0 + wn0 + nf * 8 + lk * 2;
                #pragma unroll
                for (int e = 0; e < 2; e++) {
                    float v = acc[mf][nf][half * 2 + e];
                    int cc = col + e;
                    if (b1) v += b1[cc];
                    if (b2) v += b2[cc];
                    if (R)  v += R[(long)row * N + cc];
                    if (act == 1)      v = fmaxf(v, 0.f);
                    else if (act == 2) v = tanhf(v);
                    C[(long)row * N + cc] = v;
                }
            }
        }
    }
}

// ---------------- layernorm ----------------
__global__ void k_layernorm(const float* __restrict__ X, const float* __restrict__ g,
                            const float* __restrict__ b, float* __restrict__ Y)
{
    __shared__ float rs[8], rq[8];
    int r = blockIdx.x, t = threadIdx.x;
    const float* x = X + (long)r * 512;
    float v0 = x[t], v1 = x[t + 256];
    float s = v0 + v1, q = v0 * v0 + v1 * v1;
    #pragma unroll
    for (int o = 16; o; o >>= 1) {
        s += __shfl_down_sync(0xffffffffu, s, o);
        q += __shfl_down_sync(0xffffffffu, q, o);
    }
    if ((t & 31) == 0) { rs[t >> 5] = s; rq[t >> 5] = q; }
    __syncthreads();
    if (t == 0) {
        float ts = 0.f, tq = 0.f;
        for (int i = 0; i < 8; i++) { ts += rs[i]; tq += rq[i]; }
        rs[0] = ts; rq[0] = tq;
    }
    __syncthreads();
    float m   = rs[0] * (1.f / 512.f);
    float var = rq[0] * (1.f / 512.f) - m * m;
    float inv = 1.0f / sqrtf(var + 1e-5f);
    Y[(long)r * 512 + t]       = (v0 - m) * inv * g[t]       + b[t];
    Y[(long)r * 512 + t + 256] = (v1 - m) * inv * g[t + 256] + b[t + 256];
}

__global__ void k_sgmean(const float* __restrict__ enc, float* __restrict__ sg)
{
    int t = threadIdx.x;
    float a = 0.f;
    for (int f = 0; f < FF; f++) a += enc[(long)(BB + f) * 512 + t];
    sg[t] = a * (1.0f / FF);
}

__global__ void k_svec(const float* __restrict__ w_hh, const float* __restrict__ sg,
                       float* __restrict__ S)
{
    int gw = (blockIdx.x * blockDim.x + threadIdx.x) >> 5;
    int l  = threadIdx.x & 31;
    if (gw >= GSEL) return;
    int orig = ((gw >> 9) << 10) + (gw & 511);
    const float* row = w_hh + (long)orig * 1024 + 512;
    float a = 0.f;
    for (int j = l; j < 512; j += 32) a += row[j] * sg[j];
    #pragma unroll
    for (int o = 16; o; o >>= 1) a += __shfl_down_sync(0xffffffffu, a, o);
    if (l == 0) S[gw] = a;
}

__global__ void k_lstm(const float* __restrict__ gates, const float* __restrict__ qg,
                       float* __restrict__ c, float* __restrict__ h, int first)
{
    int i = blockIdx.x * blockDim.x + threadIdx.x;
    if (i >= BB * 512) return;
    int b = i >> 9, j = i & 511;
    const float* gr = gates + (long)b * GSEL;
    float gi = gr[j], gf = gr[j + 512], gg = gr[j + 1024], go = gr[j + 1536];
    float cp = first ? 0.f : c[i];
    float cn = (1.f / (1.f + expf(-gf))) * cp + (1.f / (1.f + expf(-gi))) * tanhf(gg);
    c[i] = cn;
    h[i] = qg[i] + (1.f / (1.f + expf(-go))) * tanhf(cn);
}

__global__ void k_sgnorm(const float* __restrict__ sg, float* __restrict__ sgn)
{
    __shared__ float red[16];
    int t = threadIdx.x;
    float v = sg[t], q = v * v;
    #pragma unroll
    for (int o = 16; o; o >>= 1) q += __shfl_down_sync(0xffffffffu, q, o);
    if ((t & 31) == 0) red[t >> 5] = q;
    __syncthreads();
    if (t == 0) { float s = 0.f; for (int i = 0; i < 16; i++) s += red[i]; red[0] = sqrtf(s); }
    __syncthreads();
    sgn[t] = v / fmaxf(red[0], 1e-12f);
}

__global__ void k_final(const float* __restrict__ h, const float* __restrict__ sgn,
                        float* __restrict__ out)
{
    int gw = (blockIdx.x * blockDim.x + threadIdx.x) >> 5;
    int l  = threadIdx.x & 31;
    if (gw >= BB) return;
    const float* hr = h + (long)gw * 512;
    float d = 0.f, q = 0.f;
    for (int j = l; j < 512; j += 32) { float v = hr[j]; d += v * sgn[j]; q += v * v; }
    #pragma unroll
    for (int o = 16; o; o >>= 1) {
        d += __shfl_down_sync(0xffffffffu, d, o);
        q += __shfl_down_sync(0xffffffffu, q, o);
    }
    if (l == 0) out[gw] = d / fmaxf(sqrtf(q), 1e-12f);
}

// ---------------- launch ----------------
extern "C" void kernel_launch(void* const* d_in, const int* in_sizes, int n_in,
                              void* d_out, int out_size)
{
    const int*   query   = (const int*)  d_in[0];
    const int*   support = (const int*)  d_in[1];
    const int*   qlc     = (const int*)  d_in[2];
    const int*   qrc     = (const int*)  d_in[4];
    const int*   slc     = (const int*)  d_in[6];
    const int*   src_    = (const int*)  d_in[8];
    const float* emb     = (const float*)d_in[10];
    const float* gcn_w   = (const float*)d_in[11];
    const float* gcn_wb  = (const float*)d_in[12];
    const float* gcn_b   = (const float*)d_in[13];
    const float* p1_w    = (const float*)d_in[14];
    const float* p1_b    = (const float*)d_in[15];
    const float* p2_w    = (const float*)d_in[16];
    const float* p2_b    = (const float*)d_in[17];
    const float* ln_g    = (const float*)d_in[18];
    const float* ln_b    = (const float*)d_in[19];
    const float* w_ih    = (const float*)d_in[20];
    const float* w_hh    = (const float*)d_in[21];
    const float* b_ih    = (const float*)d_in[22];
    const float* b_hh    = (const float*)d_in[23];
    float* out = (float*)d_out;

    float *catmean, *x, *h1, *o, *enc, *sg, *sgn, *Wih, *Whh, *bsel, *Svec, *G0, *gates, *c, *hcur;
    cudaGetSymbolAddress((void**)&catmean, g_catmean);
    cudaGetSymbolAddress((void**)&x,       g_x);
    cudaGetSymbolAddress((void**)&h1,      g_h1);
    cudaGetSymbolAddress((void**)&o,       g_o);
    cudaGetSymbolAddress((void**)&enc,     g_enc);
    cudaGetSymbolAddress((void**)&sg,      g_sg);
    cudaGetSymbolAddress((void**)&sgn,     g_sgn);
    cudaGetSymbolAddress((void**)&Wih,     g_Wih);
    cudaGetSymbolAddress((void**)&Whh,     g_Whh);
    cudaGetSymbolAddress((void**)&bsel,    g_bsel);
    cudaGetSymbolAddress((void**)&Svec,    g_Svec);
    cudaGetSymbolAddress((void**)&G0,      g_G0);
    cudaGetSymbolAddress((void**)&gates,   g_gates);
    cudaGetSymbolAddress((void**)&c,       g_c);
    cudaGetSymbolAddress((void**)&hcur,    g_hcur);

    // 1. selected-gate weight prep
    k_prep<<<(GSEL * 512) / 512, 512>>>(w_ih, w_hh, b_ih, b_hh, Wih, Whh, bsel);

    // 2. neighbor encoder gather + top-k + mean -> catmean (4106 x 512)
    k_neighbor<<<MCM, 256>>>(query, support, qlc, qrc, slc, src_, emb, catmean);

    // 3. GCN: tanh(catmean @ gcn_w^T + wb + b) -> x (reshaped 2053 x 512)
    k_gemm_mma<<<dim3(2, 33), 256>>>(catmean, gcn_w, gcn_wb, gcn_b, nullptr, x, MCM, 256, 512, 2);

    // 4. support encoder MLP + LN
    k_gemm_mma<<<dim3(8, 17), 256>>>(x,  p1_w, p1_b, nullptr, nullptr, h1, MX, 1024, 512, 1);
    k_gemm_mma<<<dim3(4, 17), 256>>>(h1, p2_w, p2_b, nullptr, x,       o,  MX, 512, 1024, 0);
    k_layernorm<<<MX, 256>>>(o, ln_g, ln_b, enc);
    k_sgmean<<<1, 512>>>(enc, sg);

    // 5. G0 = query_g @ Wih_sel^T + (b_ih + b_hh)_sel
    k_gemm_mma<<<dim3(16, 16), 256>>>(enc, Wih, bsel, nullptr, nullptr, G0, BB, GSEL, 512, 0);
    k_svec<<<(GSEL * 32) / 256, 256>>>(w_hh, sg, Svec);

    // 6. LSTM steps
    k_lstm<<<(BB * 512) / 256, 256>>>(G0, enc, c, hcur, 1);
    for (int s = 1; s < 4; s++) {
        k_gemm_mma<<<dim3(16, 16), 256>>>(hcur, Whh, Svec, nullptr, G0, gates, BB, GSEL, 512, 0);
        k_lstm<<<(BB * 512) / 256, 256>>>(gates, enc, c, hcur, 0);
    }

    // 7. cosine output
    k_sgnorm<<<1, 512>>>(sg, sgn);
    k_final<<<(BB * 32) / 256, 256>>>(hcur, sgn, out);
}

// round 13
// speedup vs baseline: 1.4506x; 1.2602x over previous
#include <cuda_runtime.h>
#include <cstdint>
#include <math.h>

// ---------------- problem constants ----------------
#define BB   2048
#define FF   5
#define NNB  64          // neighbors per node
#define KK   32          // top-k
#define DD   256         // emb dim
#define GSEL 2048        // selected gate width (4 * 512)
#define MCM  (2*BB + 2*FF)   // 4106 catmean rows
#define MX   (BB + FF)       // 2053 encoder rows

// ---------------- scratch (static device globals; no allocation) ----------------
__device__ float g_catmean[(size_t)MCM * 512];
__device__ float g_x     [(size_t)MX * 512];
__device__ float g_h1    [(size_t)MX * 1024];
__device__ float g_o     [(size_t)MX * 512];
__device__ float g_enc   [(size_t)MX * 512];
__device__ float g_sg    [512];
__device__ float g_sgn   [512];
__device__ float g_Wih   [(size_t)GSEL * 512];
__device__ float g_Whh   [(size_t)GSEL * 512];
__device__ float g_bsel  [GSEL];
__device__ float g_Svec  [GSEL];
__device__ float g_G0    [(size_t)BB * GSEL];
__device__ float g_gates [(size_t)BB * GSEL];
__device__ float g_c     [(size_t)BB * 512];
__device__ float g_hcur  [(size_t)BB * 512];

__device__ __forceinline__ uint32_t f2tf32(float x) {
    uint32_t r;
    asm("cvt.rna.tf32.f32 %0, %1;" : "=r"(r) : "f"(x));
    return r;
}

// ---------------- kernel 1: weight selection prep ----------------
__global__ void k_prep(const float* __restrict__ w_ih, const float* __restrict__ w_hh,
                       const float* __restrict__ b_ih, const float* __restrict__ b_hh,
                       float* __restrict__ Wih, float* __restrict__ Whh, float* __restrict__ bsel)
{
    int i = blockIdx.x * blockDim.x + threadIdx.x;
    if (i >= GSEL * 512) return;
    int r = i >> 9, k = i & 511;
    int orig = ((r >> 9) << 10) + (r & 511);
    Wih[i] = w_ih[(long)orig * 512 + k];
    Whh[i] = w_hh[(long)orig * 1024 + k];
    if (k == 0) bsel[r] = b_ih[orig] + b_hh[orig];
}

// ---------------- kernel 2: neighbor encode (sim + exact top-k + mean) ----------------
__global__ void __launch_bounds__(256) k_neighbor(
    const int* __restrict__ query, const int* __restrict__ support,
    const int* __restrict__ qlc, const int* __restrict__ qrc,
    const int* __restrict__ slc, const int* __restrict__ src_,
    const float* __restrict__ emb, float* __restrict__ catmean)
{
    __shared__ int   s_conn[2 * NNB];
    __shared__ float s_center[DD];
    __shared__ float s_sim[NNB];
    __shared__ int   s_sel[NNB];
    __shared__ float s_red[9];

    int tid = threadIdx.x;
    int blk = blockIdx.x;
    const int* conn; int id;
    if (blk < 2 * BB) {
        int b = blk >> 1, s = blk & 1;
        conn = (s ? qrc : qlc) + (long)b * (2 * NNB);
        id = query[2 * b + s];
    } else {
        int t = blk - 2 * BB; int f = t >> 1, s = t & 1;
        conn = (s ? src_ : slc) + (long)f * (2 * NNB);
        id = support[2 * f + s];
    }
    if (tid < 2 * NNB) s_conn[tid] = conn[tid];

    float cv = emb[(long)id * DD + tid];
    s_center[tid] = cv;
    float cs = cv * cv;
    #pragma unroll
    for (int o = 16; o; o >>= 1) cs += __shfl_down_sync(0xffffffffu, cs, o);
    if ((tid & 31) == 0) s_red[tid >> 5] = cs;
    __syncthreads();
    if (tid == 0) { float t = 0.f; for (int i = 0; i < 8; i++) t += s_red[i]; s_red[8] = sqrtf(t); }
    __syncthreads();
    float cnorm = s_red[8];

    int w = tid >> 5, l = tid & 31;
    for (int n = w; n < NNB; n += 8) {
        const float* e = emb + (long)s_conn[2 * n + 1] * DD;
        float d = 0.f, q = 0.f;
        #pragma unroll
        for (int i = l; i < DD; i += 32) { float v = e[i]; d += v * s_center[i]; q += v * v; }
        #pragma unroll
        for (int o = 16; o; o >>= 1) {
            d += __shfl_down_sync(0xffffffffu, d, o);
            q += __shfl_down_sync(0xffffffffu, q, o);
        }
        if (l == 0) s_sim[n] = d / fmaxf(cnorm * sqrtf(q), 1e-8f);
    }
    __syncthreads();

    if (tid < NNB) {
        float sn = s_sim[tid]; int rank = 0;
        #pragma unroll
        for (int m = 0; m < NNB; m++) {
            float sm = s_sim[m];
            rank += (sm > sn) || (sm == sn && m < tid);
        }
        s_sel[tid] = (rank < KK);
    }
    __syncthreads();

    float ra = 0.f, ea = 0.f;
    for (int n = 0; n < NNB; n++) {
        if (s_sel[n]) {
            ra += emb[(long)s_conn[2 * n]     * DD + tid];
            ea += emb[(long)s_conn[2 * n + 1] * DD + tid];
        }
    }
    catmean[(long)blk * 512 + tid]      = ra * (1.0f / KK);
    catmean[(long)blk * 512 + DD + tid] = ea * (1.0f / KK);
}

// ---------------- tf32 mma.sync GEMM: C = act(A @ W^T + b1 + b2 + R) ----------------
// A:(M,K) row-major, W:(N,K) row-major. N%128==0, K%16==0, M guarded.
// CTA tile 64x128, 128 threads (4 warps, 1x4), warp tile 64x32, m16n8k8 frags.
// Double-buffered SMEM, one barrier per K-chunk, 3 CTAs/SM target.
#define SPAD 20   // smem row stride in floats (conflict-free fragment loads)

__global__ void __launch_bounds__(128, 3) k_gemm_mma(
    const float* __restrict__ A, const float* __restrict__ W,
    const float* __restrict__ b1, const float* __restrict__ b2,
    const float* __restrict__ R, float* __restrict__ C,
    int M, int N, int K, int act)
{
    __shared__ float As[2][64 * SPAD];
    __shared__ float Bs[2][128 * SPAD];

    const int tid = threadIdx.x;
    const int wid = tid >> 5, lane = tid & 31;
    const int bn0 = blockIdx.x * 128, bm0 = blockIdx.y * 64;
    const int wn0 = wid * 32;               // warp n offset (0,32,64,96)
    const int lg = lane >> 2;               // lane group 0..7
    const int lk = lane & 3;                // k-within-4

    // loaders: A -> thread covers (row = tid/2, 8 cols); B -> thread covers (row = tid, 16 cols)
    const int ra = tid >> 1, ca = (tid & 1) * 8;
    const int rb = tid;

    float acc[4][4][4];
    #pragma unroll
    for (int mf = 0; mf < 4; mf++)
        #pragma unroll
        for (int nf = 0; nf < 4; nf++)
            #pragma unroll
            for (int j = 0; j < 4; j++) acc[mf][nf][j] = 0.f;

    float4 pa0, pa1, pb0, pb1, pb2, pb3;
    // prefetch chunk 0
    {
        int gr = bm0 + ra;
        if (gr < M) {
            pa0 = *(const float4*)(A + (long)gr * K + ca);
            pa1 = *(const float4*)(A + (long)gr * K + ca + 4);
        } else { pa0 = make_float4(0,0,0,0); pa1 = pa0; }
        const float* wr = W + (long)(bn0 + rb) * K;
        pb0 = *(const float4*)(wr + 0);
        pb1 = *(const float4*)(wr + 4);
        pb2 = *(const float4*)(wr + 8);
        pb3 = *(const float4*)(wr + 12);
    }
    // store chunk 0 -> stage 0
    {
        float* a = &As[0][ra * SPAD + ca];
        a[0]=__uint_as_float(f2tf32(pa0.x)); a[1]=__uint_as_float(f2tf32(pa0.y));
        a[2]=__uint_as_float(f2tf32(pa0.z)); a[3]=__uint_as_float(f2tf32(pa0.w));
        a[4]=__uint_as_float(f2tf32(pa1.x)); a[5]=__uint_as_float(f2tf32(pa1.y));
        a[6]=__uint_as_float(f2tf32(pa1.z)); a[7]=__uint_as_float(f2tf32(pa1.w));
        float* b = &Bs[0][rb * SPAD];
        b[0] =__uint_as_float(f2tf32(pb0.x)); b[1] =__uint_as_float(f2tf32(pb0.y));
        b[2] =__uint_as_float(f2tf32(pb0.z)); b[3] =__uint_as_float(f2tf32(pb0.w));
        b[4] =__uint_as_float(f2tf32(pb1.x)); b[5] =__uint_as_float(f2tf32(pb1.y));
        b[6] =__uint_as_float(f2tf32(pb1.z)); b[7] =__uint_as_float(f2tf32(pb1.w));
        b[8] =__uint_as_float(f2tf32(pb2.x)); b[9] =__uint_as_float(f2tf32(pb2.y));
        b[10]=__uint_as_float(f2tf32(pb2.z)); b[11]=__uint_as_float(f2tf32(pb2.w));
        b[12]=__uint_as_float(f2tf32(pb3.x)); b[13]=__uint_as_float(f2tf32(pb3.y));
        b[14]=__uint_as_float(f2tf32(pb3.z)); b[15]=__uint_as_float(f2tf32(pb3.w));
    }
    __syncthreads();

    const int chunks = K >> 4;
    for (int kc = 0; kc < chunks; kc++) {
        const int st = kc & 1;
        const bool more = (kc + 1 < chunks);

        // prefetch next chunk (LDGs resolve during compute below)
        if (more) {
            const long kb = (long)((kc + 1) << 4);
            int gr = bm0 + ra;
            if (gr < M) {
                pa0 = *(const float4*)(A + (long)gr * K + kb + ca);
                pa1 = *(const float4*)(A + (long)gr * K + kb + ca + 4);
            } else { pa0 = make_float4(0,0,0,0); pa1 = pa0; }
            const float* wr = W + (long)(bn0 + rb) * K + kb;
            pb0 = *(const float4*)(wr + 0);
            pb1 = *(const float4*)(wr + 4);
            pb2 = *(const float4*)(wr + 8);
            pb3 = *(const float4*)(wr + 12);
        }

        // compute 2 k8-steps from stage st
        #pragma unroll
        for (int ks = 0; ks < 2; ks++) {
            const int k0 = ks * 8;
            uint32_t af[4][4];
            #pragma unroll
            for (int mf = 0; mf < 4; mf++) {
                int r0 = mf * 16 + lg;
                af[mf][0] = __float_as_uint(As[st][(r0)     * SPAD + k0 + lk]);
                af[mf][1] = __float_as_uint(As[st][(r0 + 8) * SPAD + k0 + lk]);
                af[mf][2] = __float_as_uint(As[st][(r0)     * SPAD + k0 + lk + 4]);
                af[mf][3] = __float_as_uint(As[st][(r0 + 8) * SPAD + k0 + lk + 4]);
            }
            uint32_t bf[4][2];
            #pragma unroll
            for (int nf = 0; nf < 4; nf++) {
                int n = wn0 + nf * 8 + lg;
                bf[nf][0] = __float_as_uint(Bs[st][n * SPAD + k0 + lk]);
                bf[nf][1] = __float_as_uint(Bs[st][n * SPAD + k0 + lk + 4]);
            }
            #pragma unroll
            for (int mf = 0; mf < 4; mf++)
                #pragma unroll
                for (int nf = 0; nf < 4; nf++) {
                    asm volatile(
                        "mma.sync.aligned.m16n8k8.row.col.f32.tf32.tf32.f32 "
                        "{%0,%1,%2,%3}, {%4,%5,%6,%7}, {%8,%9}, {%0,%1,%2,%3};"
                        : "+f"(acc[mf][nf][0]), "+f"(acc[mf][nf][1]),
                          "+f"(acc[mf][nf][2]), "+f"(acc[mf][nf][3])
                        : "r"(af[mf][0]), "r"(af[mf][1]), "r"(af[mf][2]), "r"(af[mf][3]),
                          "r"(bf[nf][0]), "r"(bf[nf][1]));
                }
        }

        // store next chunk into the other stage
        if (more) {
            const int st2 = st ^ 1;
            float* a = &As[st2][ra * SPAD + ca];
            a[0]=__uint_as_float(f2tf32(pa0.x)); a[1]=__uint_as_float(f2tf32(pa0.y));
            a[2]=__uint_as_float(f2tf32(pa0.z)); a[3]=__uint_as_float(f2tf32(pa0.w));
            a[4]=__uint_as_float(f2tf32(pa1.x)); a[5]=__uint_as_float(f2tf32(pa1.y));
            a[6]=__uint_as_float(f2tf32(pa1.z)); a[7]=__uint_as_float(f2tf32(pa1.w));
            float* b = &Bs[st2][rb * SPAD];
            b[0] =__uint_as_float(f2tf32(pb0.x)); b[1] =__uint_as_float(f2tf32(pb0.y));
            b[2] =__uint_as_float(f2tf32(pb0.z)); b[3] =__uint_as_float(f2tf32(pb0.w));
            b[4] =__uint_as_float(f2tf32(pb1.x)); b[5] =__uint_as_float(f2tf32(pb1.y));
            b[6] =__uint_as_float(f2tf32(pb1.z)); b[7] =__uint_as_float(f2tf32(pb1.w));
            b[8] =__uint_as_float(f2tf32(pb2.x)); b[9] =__uint_as_float(f2tf32(pb2.y));
            b[10]=__uint_as_float(f2tf32(pb2.z)); b[11]=__uint_as_float(f2tf32(pb2.w));
            b[12]=__uint_as_float(f2tf32(pb3.x)); b[13]=__uint_as_float(f2tf32(pb3.y));
            b[14]=__uint_as_float(f2tf32(pb3.z)); b[15]=__uint_as_float(f2tf32(pb3.w));
        }
        __syncthreads();
    }

    // epilogue: c0:(row,col) c1:(row,col+1) c2:(row+8,col) c3:(row+8,col+1)
    #pragma unroll
    for (int mf = 0; mf < 4; mf++) {
        #pragma unroll
        for (int half = 0; half < 2; half++) {
            int row = bm0 + mf * 16 + lg + half * 8;
            if (row >= M) continue;
            #pragma unroll
            for (int nf = 0; nf < 4; nf++) {
                int col = bn0 + wn0 + nf * 8 + lk * 2;
                #pragma unroll
                for (int e = 0; e < 2; e++) {
                    float v = acc[mf][nf][half * 2 + e];
                    int cc = col + e;
                    if (b1) v += b1[cc];
                    if (b2) v += b2[cc];
                    if (R)  v += R[(long)row * N + cc];
                    if (act == 1)      v = fmaxf(v, 0.f);
                    else if (act == 2) v = tanhf(v);
                    C[(long)row * N + cc] = v;
                }
            }
        }
    }
}

// ---------------- layernorm ----------------
__global__ void k_layernorm(const float* __restrict__ X, const float* __restrict__ g,
                            const float* __restrict__ b, float* __restrict__ Y)
{
    __shared__ float rs[8], rq[8];
    int r = blockIdx.x, t = threadIdx.x;
    const float* x = X + (long)r * 512;
    float v0 = x[t], v1 = x[t + 256];
    float s = v0 + v1, q = v0 * v0 + v1 * v1;
    #pragma unroll
    for (int o = 16; o; o >>= 1) {
        s += __shfl_down_sync(0xffffffffu, s, o);
        q += __shfl_down_sync(0xffffffffu, q, o);
    }
    if ((t & 31) == 0) { rs[t >> 5] = s; rq[t >> 5] = q; }
    __syncthreads();
    if (t == 0) {
        float ts = 0.f, tq = 0.f;
        for (int i = 0; i < 8; i++) { ts += rs[i]; tq += rq[i]; }
        rs[0] = ts; rq[0] = tq;
    }
    __syncthreads();
    float m   = rs[0] * (1.f / 512.f);
    float var = rq[0] * (1.f / 512.f) - m * m;
    float inv = 1.0f / sqrtf(var + 1e-5f);
    Y[(long)r * 512 + t]       = (v0 - m) * inv * g[t]       + b[t];
    Y[(long)r * 512 + t + 256] = (v1 - m) * inv * g[t + 256] + b[t + 256];
}

__global__ void k_sgmean(const float* __restrict__ enc, float* __restrict__ sg)
{
    int t = threadIdx.x;
    float a = 0.f;
    for (int f = 0; f < FF; f++) a += enc[(long)(BB + f) * 512 + t];
    sg[t] = a * (1.0f / FF);
}

__global__ void k_svec(const float* __restrict__ w_hh, const float* __restrict__ sg,
                       float* __restrict__ S)
{
    int gw = (blockIdx.x * blockDim.x + threadIdx.x) >> 5;
    int l  = threadIdx.x & 31;
    if (gw >= GSEL) return;
    int orig = ((gw >> 9) << 10) + (gw & 511);
    const float* row = w_hh + (long)orig * 1024 + 512;
    float a = 0.f;
    for (int j = l; j < 512; j += 32) a += row[j] * sg[j];
    #pragma unroll
    for (int o = 16; o; o >>= 1) a += __shfl_down_sync(0xffffffffu, a, o);
    if (l == 0) S[gw] = a;
}

__global__ void k_lstm(const float* __restrict__ gates, const float* __restrict__ qg,
                       float* __restrict__ c, float* __restrict__ h, int first)
{
    int i = blockIdx.x * blockDim.x + threadIdx.x;
    if (i >= BB * 512) return;
    int b = i >> 9, j = i & 511;
    const float* gr = gates + (long)b * GSEL;
    float gi = gr[j], gf = gr[j + 512], gg = gr[j + 1024], go = gr[j + 1536];
    float cp = first ? 0.f : c[i];
    float cn = (1.f / (1.f + expf(-gf))) * cp + (1.f / (1.f + expf(-gi))) * tanhf(gg);
    c[i] = cn;
    h[i] = qg[i] + (1.f / (1.f + expf(-go))) * tanhf(cn);
}

__global__ void k_sgnorm(const float* __restrict__ sg, float* __restrict__ sgn)
{
    __shared__ float red[16];
    int t = threadIdx.x;
    float v = sg[t], q = v * v;
    #pragma unroll
    for (int o = 16; o; o >>= 1) q += __shfl_down_sync(0xffffffffu, q, o);
    if ((t & 31) == 0) red[t >> 5] = q;
    __syncthreads();
    if (t == 0) { float s = 0.f; for (int i = 0; i < 16; i++) s += red[i]; red[0] = sqrtf(s); }
    __syncthreads();
    sgn[t] = v / fmaxf(red[0], 1e-12f);
}

__global__ void k_final(const float* __restrict__ h, const float* __restrict__ sgn,
                        float* __restrict__ out)
{
    int gw = (blockIdx.x * blockDim.x + threadIdx.x) >> 5;
    int l  = threadIdx.x & 31;
    if (gw >= BB) return;
    const float* hr = h + (long)gw * 512;
    float d = 0.f, q = 0.f;
    for (int j = l; j < 512; j += 32) { float v = hr[j]; d += v * sgn[j]; q += v * v; }
    #pragma unroll
    for (int o = 16; o; o >>= 1) {
        d += __shfl_down_sync(0xffffffffu, d, o);
        q += __shfl_down_sync(0xffffffffu, q, o);
    }
    if (l == 0) out[gw] = d / fmaxf(sqrtf(q), 1e-12f);
}

// ---------------- launch ----------------
extern "C" void kernel_launch(void* const* d_in, const int* in_sizes, int n_in,
                              void* d_out, int out_size)
{
    const int*   query   = (const int*)  d_in[0];
    const int*   support = (const int*)  d_in[1];
    const int*   qlc     = (const int*)  d_in[2];
    const int*   qrc     = (const int*)  d_in[4];
    const int*   slc     = (const int*)  d_in[6];
    const int*   src_    = (const int*)  d_in[8];
    const float* emb     = (const float*)d_in[10];
    const float* gcn_w   = (const float*)d_in[11];
    const float* gcn_wb  = (const float*)d_in[12];
    const float* gcn_b   = (const float*)d_in[13];
    const float* p1_w    = (const float*)d_in[14];
    const float* p1_b    = (const float*)d_in[15];
    const float* p2_w    = (const float*)d_in[16];
    const float* p2_b    = (const float*)d_in[17];
    const float* ln_g    = (const float*)d_in[18];
    const float* ln_b    = (const float*)d_in[19];
    const float* w_ih    = (const float*)d_in[20];
    const float* w_hh    = (const float*)d_in[21];
    const float* b_ih    = (const float*)d_in[22];
    const float* b_hh    = (const float*)d_in[23];
    float* out = (float*)d_out;

    float *catmean, *x, *h1, *o, *enc, *sg, *sgn, *Wih, *Whh, *bsel, *Svec, *G0, *gates, *c, *hcur;
    cudaGetSymbolAddress((void**)&catmean, g_catmean);
    cudaGetSymbolAddress((void**)&x,       g_x);
    cudaGetSymbolAddress((void**)&h1,      g_h1);
    cudaGetSymbolAddress((void**)&o,       g_o);
    cudaGetSymbolAddress((void**)&enc,     g_enc);
    cudaGetSymbolAddress((void**)&sg,      g_sg);
    cudaGetSymbolAddress((void**)&sgn,     g_sgn);
    cudaGetSymbolAddress((void**)&Wih,     g_Wih);
    cudaGetSymbolAddress((void**)&Whh,     g_Whh);
    cudaGetSymbolAddress((void**)&bsel,    g_bsel);
    cudaGetSymbolAddress((void**)&Svec,    g_Svec);
    cudaGetSymbolAddress((void**)&G0,      g_G0);
    cudaGetSymbolAddress((void**)&gates,   g_gates);
    cudaGetSymbolAddress((void**)&c,       g_c);
    cudaGetSymbolAddress((void**)&hcur,    g_hcur);

    // 1. selected-gate weight prep
    k_prep<<<(GSEL * 512) / 512, 512>>>(w_ih, w_hh, b_ih, b_hh, Wih, Whh, bsel);

    // 2. neighbor encoder gather + top-k + mean -> catmean (4106 x 512)
    k_neighbor<<<MCM, 256>>>(query, support, qlc, qrc, slc, src_, emb, catmean);

    // 3. GCN: tanh(catmean @ gcn_w^T + wb + b) -> x (reshaped 2053 x 512)
    k_gemm_mma<<<dim3(2, 65), 128>>>(catmean, gcn_w, gcn_wb, gcn_b, nullptr, x, MCM, 256, 512, 2);

    // 4. support encoder MLP + LN
    k_gemm_mma<<<dim3(8, 33), 128>>>(x,  p1_w, p1_b, nullptr, nullptr, h1, MX, 1024, 512, 1);
    k_gemm_mma<<<dim3(4, 33), 128>>>(h1, p2_w, p2_b, nullptr, x,       o,  MX, 512, 1024, 0);
    k_layernorm<<<MX, 256>>>(o, ln_g, ln_b, enc);
    k_sgmean<<<1, 512>>>(enc, sg);

    // 5. G0 = query_g @ Wih_sel^T + (b_ih + b_hh)_sel
    k_gemm_mma<<<dim3(16, 32), 128>>>(enc, Wih, bsel, nullptr, nullptr, G0, BB, GSEL, 512, 0);
    k_svec<<<(GSEL * 32) / 256, 256>>>(w_hh, sg, Svec);

    // 6. LSTM steps
    k_lstm<<<(BB * 512) / 256, 256>>>(G0, enc, c, hcur, 1);
    for (int s = 1; s < 4; s++) {
        k_gemm_mma<<<dim3(16, 32), 128>>>(hcur, Whh, Svec, nullptr, G0, gates, BB, GSEL, 512, 0);
        k_lstm<<<(BB * 512) / 256, 256>>>(gates, enc, c, hcur, 0);
    }

    // 7. cosine output
    k_sgnorm<<<1, 512>>>(sg, sgn);
    k_final<<<(BB * 32) / 256, 256>>>(hcur, sgn, out);
}

// round 16
// speedup vs baseline: 1.7541x; 1.2093x over previous
#include <cuda_runtime.h>
#include <cstdint>
#include <math.h>

// ---------------- problem constants ----------------
#define BB   2048
#define FF   5
#define NNB  64          // neighbors per node
#define KK   32          // top-k
#define DD   256         // emb dim
#define GSEL 2048        // selected gate width (4 * 512)
#define MCM  (2*BB + 2*FF)   // 4106 catmean rows
#define MX   (BB + FF)       // 2053 encoder rows

// ---------------- scratch (static device globals; no allocation) ----------------
__device__ float g_catmean[(size_t)MCM * 512];
__device__ float g_x     [(size_t)MX * 512];
__device__ float g_h1    [(size_t)MX * 1024];
__device__ float g_o     [(size_t)MX * 512];
__device__ float g_enc   [(size_t)MX * 512];
__device__ float g_sg    [512];
__device__ float g_sgn   [512];
__device__ float g_Wih   [(size_t)GSEL * 512];
__device__ float g_Whh   [(size_t)GSEL * 512];
__device__ float g_bsel  [GSEL];
__device__ float g_Svec  [GSEL];
__device__ float g_G0    [(size_t)BB * GSEL];
__device__ float g_gates [(size_t)BB * GSEL];
__device__ float g_c     [(size_t)BB * 512];
__device__ float g_hcur  [(size_t)BB * 512];

__device__ __forceinline__ uint32_t f2tf32(float x) {
    uint32_t r;
    asm("cvt.rna.tf32.f32 %0, %1;" : "=r"(r) : "f"(x));
    return r;
}

// ---------------- kernel 1: weight selection prep ----------------
__global__ void k_prep(const float* __restrict__ w_ih, const float* __restrict__ w_hh,
                       const float* __restrict__ b_ih, const float* __restrict__ b_hh,
                       float* __restrict__ Wih, float* __restrict__ Whh, float* __restrict__ bsel)
{
    int i = blockIdx.x * blockDim.x + threadIdx.x;
    if (i >= GSEL * 512) return;
    int r = i >> 9, k = i & 511;
    int orig = ((r >> 9) << 10) + (r & 511);
    Wih[i] = w_ih[(long)orig * 512 + k];
    Whh[i] = w_hh[(long)orig * 1024 + k];
    if (k == 0) bsel[r] = b_ih[orig] + b_hh[orig];
}

// ---------------- kernel 2: neighbor encode (sim + exact top-k + mean) ----------------
__global__ void __launch_bounds__(256) k_neighbor(
    const int* __restrict__ query, const int* __restrict__ support,
    const int* __restrict__ qlc, const int* __restrict__ qrc,
    const int* __restrict__ slc, const int* __restrict__ src_,
    const float* __restrict__ emb, float* __restrict__ catmean)
{
    __shared__ int   s_conn[2 * NNB];
    __shared__ float s_center[DD];
    __shared__ float s_sim[NNB];
    __shared__ int   s_sel[NNB];
    __shared__ float s_red[9];

    int tid = threadIdx.x;
    int blk = blockIdx.x;
    const int* conn; int id;
    if (blk < 2 * BB) {
        int b = blk >> 1, s = blk & 1;
        conn = (s ? qrc : qlc) + (long)b * (2 * NNB);
        id = query[2 * b + s];
    } else {
        int t = blk - 2 * BB; int f = t >> 1, s = t & 1;
        conn = (s ? src_ : slc) + (long)f * (2 * NNB);
        id = support[2 * f + s];
    }
    if (tid < 2 * NNB) s_conn[tid] = conn[tid];

    float cv = emb[(long)id * DD + tid];
    s_center[tid] = cv;
    float cs = cv * cv;
    #pragma unroll
    for (int o = 16; o; o >>= 1) cs += __shfl_down_sync(0xffffffffu, cs, o);
    if ((tid & 31) == 0) s_red[tid >> 5] = cs;
    __syncthreads();
    if (tid == 0) { float t = 0.f; for (int i = 0; i < 8; i++) t += s_red[i]; s_red[8] = sqrtf(t); }
    __syncthreads();
    float cnorm = s_red[8];

    int w = tid >> 5, l = tid & 31;
    for (int n = w; n < NNB; n += 8) {
        const float* e = emb + (long)s_conn[2 * n + 1] * DD;
        float d = 0.f, q = 0.f;
        #pragma unroll
        for (int i = l; i < DD; i += 32) { float v = e[i]; d += v * s_center[i]; q += v * v; }
        #pragma unroll
        for (int o = 16; o; o >>= 1) {
            d += __shfl_down_sync(0xffffffffu, d, o);
            q += __shfl_down_sync(0xffffffffu, q, o);
        }
        if (l == 0) s_sim[n] = d / fmaxf(cnorm * sqrtf(q), 1e-8f);
    }
    __syncthreads();

    if (tid < NNB) {
        float sn = s_sim[tid]; int rank = 0;
        #pragma unroll
        for (int m = 0; m < NNB; m++) {
            float sm = s_sim[m];
            rank += (sm > sn) || (sm == sn && m < tid);
        }
        s_sel[tid] = (rank < KK);
    }
    __syncthreads();

    float ra = 0.f, ea = 0.f;
    for (int n = 0; n < NNB; n++) {
        if (s_sel[n]) {
            ra += emb[(long)s_conn[2 * n]     * DD + tid];
            ea += emb[(long)s_conn[2 * n + 1] * DD + tid];
        }
    }
    catmean[(long)blk * 512 + tid]      = ra * (1.0f / KK);
    catmean[(long)blk * 512 + DD + tid] = ea * (1.0f / KK);
}

// ---------------- tf32 mma.sync GEMM with cp.async 3-stage pipeline ----------------
// C = act(A @ W^T + b1 + b2 + R).  A:(M,K) row-major, W:(N,K) row-major.
// N%128==0, K%16==0, M guarded. CTA tile 64x128, 128 threads, warp tile 64x32.
// fp32 copied async into SMEM; RNA tf32 rounding applied at fragment load.
#define SPAD   20       // smem row stride in floats (conflict-free fragment loads)
#define STAGES 3

__device__ __forceinline__ void cp16(uint32_t dst, const void* src, bool valid) {
    asm volatile("cp.async.cg.shared.global [%0], [%1], 16, %2;"
        :: "r"(dst), "l"(src), "r"(valid ? 16u : 0u));
}
#define CP_COMMIT() asm volatile("cp.async.commit_group;" ::: "memory")
#define CP_WAIT1()  asm volatile("cp.async.wait_group 1;" ::: "memory")

__global__ void __launch_bounds__(128, 3) k_gemm_mma(
    const float* __restrict__ A, const float* __restrict__ W,
    const float* __restrict__ b1, const float* __restrict__ b2,
    const float* __restrict__ R, float* __restrict__ C,
    int M, int N, int K, int act)
{
    __shared__ float As[STAGES * 64 * SPAD];
    __shared__ float Bs[STAGES * 128 * SPAD];

    const int tid = threadIdx.x;
    const int wid = tid >> 5, lane = tid & 31;
    const int bn0 = blockIdx.x * 128, bm0 = blockIdx.y * 64;
    const int wn0 = wid * 32;               // warp n offset (0,32,64,96)
    const int lg = lane >> 2;               // lane group 0..7
    const int lk = lane & 3;                // k-within-4

    // loaders: A -> thread covers (row = tid/2, 8 cols); B -> thread covers (row = tid, 16 cols)
    const int ra = tid >> 1, ca = (tid & 1) * 8;
    const int rb = tid;
    const bool va = (bm0 + ra) < M;
    const float* gA = A + (long)(va ? (bm0 + ra) : 0) * K + ca;
    const float* gB = W + (long)(bn0 + rb) * K;

    const uint32_t sAb = (uint32_t)__cvta_generic_to_shared(As);
    const uint32_t sBb = (uint32_t)__cvta_generic_to_shared(Bs);
    const uint32_t dA = sAb + (uint32_t)(ra * SPAD + ca) * 4u;
    const uint32_t dB = sBb + (uint32_t)(rb * SPAD) * 4u;

    float acc[4][4][4];
    #pragma unroll
    for (int mf = 0; mf < 4; mf++)
        #pragma unroll
        for (int nf = 0; nf < 4; nf++)
            #pragma unroll
            for (int j = 0; j < 4; j++) acc[mf][nf][j] = 0.f;

    const int chunks = K >> 4;

    // prologue: stages 0 and 1
    #pragma unroll
    for (int s = 0; s < 2; s++) {
        const long kb = (long)s << 4;
        uint32_t da = dA + (uint32_t)(s * 64 * SPAD) * 4u;
        cp16(da,      gA + kb,     va);
        cp16(da + 16, gA + kb + 4, va);
        uint32_t db = dB + (uint32_t)(s * 128 * SPAD) * 4u;
        cp16(db,      gB + kb,      true);
        cp16(db + 16, gB + kb + 4,  true);
        cp16(db + 32, gB + kb + 8,  true);
        cp16(db + 48, gB + kb + 12, true);
        CP_COMMIT();
    }

    int st = 0;        // stage being computed
    int wst = 2;       // stage being written next
    for (int kc = 0; kc < chunks; kc++) {
        CP_WAIT1();
        __syncthreads();

        // issue loads for chunk kc+2 into stage wst
        {
            const int nk = kc + 2;
            if (nk < chunks) {
                const long kb = (long)nk << 4;
                uint32_t da = dA + (uint32_t)(wst * 64 * SPAD) * 4u;
                cp16(da,      gA + kb,     va);
                cp16(da + 16, gA + kb + 4, va);
                uint32_t db = dB + (uint32_t)(wst * 128 * SPAD) * 4u;
                cp16(db,      gB + kb,      true);
                cp16(db + 16, gB + kb + 4,  true);
                cp16(db + 32, gB + kb + 8,  true);
                cp16(db + 48, gB + kb + 12, true);
            }
            CP_COMMIT();
        }

        // compute 2 k8-steps from stage st (RNA tf32 rounding on fragment load)
        const float* Ast = As + st * 64 * SPAD;
        const float* Bst = Bs + st * 128 * SPAD;
        #pragma unroll
        for (int ks = 0; ks < 2; ks++) {
            const int k0 = ks * 8;
            uint32_t af[4][4];
            #pragma unroll
            for (int mf = 0; mf < 4; mf++) {
                int r0 = mf * 16 + lg;
                af[mf][0] = f2tf32(Ast[(r0)     * SPAD + k0 + lk]);
                af[mf][1] = f2tf32(Ast[(r0 + 8) * SPAD + k0 + lk]);
                af[mf][2] = f2tf32(Ast[(r0)     * SPAD + k0 + lk + 4]);
                af[mf][3] = f2tf32(Ast[(r0 + 8) * SPAD + k0 + lk + 4]);
            }
            uint32_t bf[4][2];
            #pragma unroll
            for (int nf = 0; nf < 4; nf++) {
                int n = wn0 + nf * 8 + lg;
                bf[nf][0] = f2tf32(Bst[n * SPAD + k0 + lk]);
                bf[nf][1] = f2tf32(Bst[n * SPAD + k0 + lk + 4]);
            }
            #pragma unroll
            for (int mf = 0; mf < 4; mf++)
                #pragma unroll
                for (int nf = 0; nf < 4; nf++) {
                    asm volatile(
                        "mma.sync.aligned.m16n8k8.row.col.f32.tf32.tf32.f32 "
                        "{%0,%1,%2,%3}, {%4,%5,%6,%7}, {%8,%9}, {%0,%1,%2,%3};"
                        : "+f"(acc[mf][nf][0]), "+f"(acc[mf][nf][1]),
                          "+f"(acc[mf][nf][2]), "+f"(acc[mf][nf][3])
                        : "r"(af[mf][0]), "r"(af[mf][1]), "r"(af[mf][2]), "r"(af[mf][3]),
                          "r"(bf[nf][0]), "r"(bf[nf][1]));
                }
        }

        st = (st == STAGES - 1) ? 0 : st + 1;
        wst = (wst == STAGES - 1) ? 0 : wst + 1;
    }

    // epilogue: c0:(row,col) c1:(row,col+1) c2:(row+8,col) c3:(row+8,col+1)
    #pragma unroll
    for (int mf = 0; mf < 4; mf++) {
        #pragma unroll
        for (int half = 0; half < 2; half++) {
            int row = bm0 + mf * 16 + lg + half * 8;
            if (row >= M) continue;
            #pragma unroll
            for (int nf = 0; nf < 4; nf++) {
                int col = bn0 + wn0 + nf * 8 + lk * 2;
                #pragma unroll
                for (int e = 0; e < 2; e++) {
                    float v = acc[mf][nf][half * 2 + e];
                    int cc = col + e;
                    if (b1) v += b1[cc];
                    if (b2) v += b2[cc];
                    if (R)  v += R[(long)row * N + cc];
                    if (act == 1)      v = fmaxf(v, 0.f);
                    else if (act == 2) v = tanhf(v);
                    C[(long)row * N + cc] = v;
                }
            }
        }
    }
}

// ---------------- layernorm ----------------
__global__ void k_layernorm(const float* __restrict__ X, const float* __restrict__ g,
                            const float* __restrict__ b, float* __restrict__ Y)
{
    __shared__ float rs[8], rq[8];
    int r = blockIdx.x, t = threadIdx.x;
    const float* x = X + (long)r * 512;
    float v0 = x[t], v1 = x[t + 256];
    float s = v0 + v1, q = v0 * v0 + v1 * v1;
    #pragma unroll
    for (int o = 16; o; o >>= 1) {
        s += __shfl_down_sync(0xffffffffu, s, o);
        q += __shfl_down_sync(0xffffffffu, q, o);
    }
    if ((t & 31) == 0) { rs[t >> 5] = s; rq[t >> 5] = q; }
    __syncthreads();
    if (t == 0) {
        float ts = 0.f, tq = 0.f;
        for (int i = 0; i < 8; i++) { ts += rs[i]; tq += rq[i]; }
        rs[0] = ts; rq[0] = tq;
    }
    __syncthreads();
    float m   = rs[0] * (1.f / 512.f);
    float var = rq[0] * (1.f / 512.f) - m * m;
    float inv = 1.0f / sqrtf(var + 1e-5f);
    Y[(long)r * 512 + t]       = (v0 - m) * inv * g[t]       + b[t];
    Y[(long)r * 512 + t + 256] = (v1 - m) * inv * g[t + 256] + b[t + 256];
}

__global__ void k_sgmean(const float* __restrict__ enc, float* __restrict__ sg)
{
    int t = threadIdx.x;
    float a = 0.f;
    for (int f = 0; f < FF; f++) a += enc[(long)(BB + f) * 512 + t];
    sg[t] = a * (1.0f / FF);
}

__global__ void k_svec(const float* __restrict__ w_hh, const float* __restrict__ sg,
                       float* __restrict__ S)
{
    int gw = (blockIdx.x * blockDim.x + threadIdx.x) >> 5;
    int l  = threadIdx.x & 31;
    if (gw >= GSEL) return;
    int orig = ((gw >> 9) << 10) + (gw & 511);
    const float* row = w_hh + (long)orig * 1024 + 512;
    float a = 0.f;
    for (int j = l; j < 512; j += 32) a += row[j] * sg[j];
    #pragma unroll
    for (int o = 16; o; o >>= 1) a += __shfl_down_sync(0xffffffffu, a, o);
    if (l == 0) S[gw] = a;
}

__global__ void k_lstm(const float* __restrict__ gates, const float* __restrict__ qg,
                       float* __restrict__ c, float* __restrict__ h, int first)
{
    int i = blockIdx.x * blockDim.x + threadIdx.x;
    if (i >= BB * 512) return;
    int b = i >> 9, j = i & 511;
    const float* gr = gates + (long)b * GSEL;
    float gi = gr[j], gf = gr[j + 512], gg = gr[j + 1024], go = gr[j + 1536];
    float cp = first ? 0.f : c[i];
    float cn = (1.f / (1.f + expf(-gf))) * cp + (1.f / (1.f + expf(-gi))) * tanhf(gg);
    c[i] = cn;
    h[i] = qg[i] + (1.f / (1.f + expf(-go))) * tanhf(cn);
}

__global__ void k_sgnorm(const float* __restrict__ sg, float* __restrict__ sgn)
{
    __shared__ float red[16];
    int t = threadIdx.x;
    float v = sg[t], q = v * v;
    #pragma unroll
    for (int o = 16; o; o >>= 1) q += __shfl_down_sync(0xffffffffu, q, o);
    if ((t & 31) == 0) red[t >> 5] = q;
    __syncthreads();
    if (t == 0) { float s = 0.f; for (int i = 0; i < 16; i++) s += red[i]; red[0] = sqrtf(s); }
    __syncthreads();
    sgn[t] = v / fmaxf(red[0], 1e-12f);
}

__global__ void k_final(const float* __restrict__ h, const float* __restrict__ sgn,
                        float* __restrict__ out)
{
    int gw = (blockIdx.x * blockDim.x + threadIdx.x) >> 5;
    int l  = threadIdx.x & 31;
    if (gw >= BB) return;
    const float* hr = h + (long)gw * 512;
    float d = 0.f, q = 0.f;
    for (int j = l; j < 512; j += 32) { float v = hr[j]; d += v * sgn[j]; q += v * v; }
    #pragma unroll
    for (int o = 16; o; o >>= 1) {
        d += __shfl_down_sync(0xffffffffu, d, o);
        q += __shfl_down_sync(0xffffffffu, q, o);
    }
    if (l == 0) out[gw] = d / fmaxf(sqrtf(q), 1e-12f);
}

// ---------------- launch ----------------
extern "C" void kernel_launch(void* const* d_in, const int* in_sizes, int n_in,
                              void* d_out, int out_size)
{
    const int*   query   = (const int*)  d_in[0];
    const int*   support = (const int*)  d_in[1];
    const int*   qlc     = (const int*)  d_in[2];
    const int*   qrc     = (const int*)  d_in[4];
    const int*   slc     = (const int*)  d_in[6];
    const int*   src_    = (const int*)  d_in[8];
    const float* emb     = (const float*)d_in[10];
    const float* gcn_w   = (const float*)d_in[11];
    const float* gcn_wb  = (const float*)d_in[12];
    const float* gcn_b   = (const float*)d_in[13];
    const float* p1_w    = (const float*)d_in[14];
    const float* p1_b    = (const float*)d_in[15];
    const float* p2_w    = (const float*)d_in[16];
    const float* p2_b    = (const float*)d_in[17];
    const float* ln_g    = (const float*)d_in[18];
    const float* ln_b    = (const float*)d_in[19];
    const float* w_ih    = (const float*)d_in[20];
    const float* w_hh    = (const float*)d_in[21];
    const float* b_ih    = (const float*)d_in[22];
    const float* b_hh    = (const float*)d_in[23];
    float* out = (float*)d_out;

    float *catmean, *x, *h1, *o, *enc, *sg, *sgn, *Wih, *Whh, *bsel, *Svec, *G0, *gates, *c, *hcur;
    cudaGetSymbolAddress((void**)&catmean, g_catmean);
    cudaGetSymbolAddress((void**)&x,       g_x);
    cudaGetSymbolAddress((void**)&h1,      g_h1);
    cudaGetSymbolAddress((void**)&o,       g_o);
    cudaGetSymbolAddress((void**)&enc,     g_enc);
    cudaGetSymbolAddress((void**)&sg,      g_sg);
    cudaGetSymbolAddress((void**)&sgn,     g_sgn);
    cudaGetSymbolAddress((void**)&Wih,     g_Wih);
    cudaGetSymbolAddress((void**)&Whh,     g_Whh);
    cudaGetSymbolAddress((void**)&bsel,    g_bsel);
    cudaGetSymbolAddress((void**)&Svec,    g_Svec);
    cudaGetSymbolAddress((void**)&G0,      g_G0);
    cudaGetSymbolAddress((void**)&gates,   g_gates);
    cudaGetSymbolAddress((void**)&c,       g_c);
    cudaGetSymbolAddress((void**)&hcur,    g_hcur);

    // 1. selected-gate weight prep
    k_prep<<<(GSEL * 512) / 512, 512>>>(w_ih, w_hh, b_ih, b_hh, Wih, Whh, bsel);

    // 2. neighbor encoder gather + top-k + mean -> catmean (4106 x 512)
    k_neighbor<<<MCM, 256>>>(query, support, qlc, qrc, slc, src_, emb, catmean);

    // 3. GCN: tanh(catmean @ gcn_w^T + wb + b) -> x (reshaped 2053 x 512)
    k_gemm_mma<<<dim3(2, 65), 128>>>(catmean, gcn_w, gcn_wb, gcn_b, nullptr, x, MCM, 256, 512, 2);

    // 4. support encoder MLP + LN
    k_gemm_mma<<<dim3(8, 33), 128>>>(x,  p1_w, p1_b, nullptr, nullptr, h1, MX, 1024, 512, 1);
    k_gemm_mma<<<dim3(4, 33), 128>>>(h1, p2_w, p2_b, nullptr, x,       o,  MX, 512, 1024, 0);
    k_layernorm<<<MX, 256>>>(o, ln_g, ln_b, enc);
    k_sgmean<<<1, 512>>>(enc, sg);

    // 5. G0 = query_g @ Wih_sel^T + (b_ih + b_hh)_sel
    k_gemm_mma<<<dim3(16, 32), 128>>>(enc, Wih, bsel, nullptr, nullptr, G0, BB, GSEL, 512, 0);
    k_svec<<<(GSEL * 32) / 256, 256>>>(w_hh, sg, Svec);

    // 6. LSTM steps
    k_lstm<<<(BB * 512) / 256, 256>>>(G0, enc, c, hcur, 1);
    for (int s = 1; s < 4; s++) {
        k_gemm_mma<<<dim3(16, 32), 128>>>(hcur, Whh, Svec, nullptr, G0, gates, BB, GSEL, 512, 0);
        k_lstm<<<(BB * 512) / 256, 256>>>(gates, enc, c, hcur, 0);
    }

    // 7. cosine output
    k_sgnorm<<<1, 512>>>(sg, sgn);
    k_final<<<(BB * 32) / 256, 256>>>(hcur, sgn, out);
}

// round 17
// speedup vs baseline: 2.0020x; 1.1413x over previous
#include <cuda_runtime.h>
#include <cstdint>
#include <math.h>

// ---------------- problem constants ----------------
#define BB   2048
#define FF   5
#define NNB  64          // neighbors per node
#define KK   32          // top-k
#define DD   256         // emb dim
#define GSEL 2048        // selected gate width (4 * 512)
#define MCM  (2*BB + 2*FF)   // 4106 catmean rows
#define MX   (BB + FF)       // 2053 encoder rows

// ---------------- scratch (static device globals; no allocation) ----------------
__device__ float g_catmean[(size_t)MCM * 512];
__device__ float g_x     [(size_t)MX * 512];
__device__ float g_h1    [(size_t)MX * 1024];
__device__ float g_o     [(size_t)MX * 512];
__device__ float g_enc   [(size_t)MX * 512];
__device__ float g_sg    [512];
__device__ float g_sgn   [512];
__device__ float g_Wih   [(size_t)GSEL * 512];
__device__ float g_Whh   [(size_t)GSEL * 512];
__device__ float g_bsel  [GSEL];
__device__ float g_Svec  [GSEL];
__device__ float g_G0    [(size_t)BB * GSEL];
__device__ float g_gates [(size_t)BB * GSEL];
__device__ float g_c     [(size_t)BB * 512];
__device__ float g_hcur  [(size_t)BB * 512];
// tf32-pre-rounded weight copies
__device__ float g_gcnw  [256 * 512];
__device__ float g_p1w   [1024 * 512];
__device__ float g_p2w   [512 * 1024];

__device__ __forceinline__ uint32_t f2tf32(float x) {
    uint32_t r;
    asm("cvt.rna.tf32.f32 %0, %1;" : "=r"(r) : "f"(x));
    return r;
}

// ---------------- kernel 1: weight selection prep (rounds to tf32) ----------------
__global__ void k_prep(const float* __restrict__ w_ih, const float* __restrict__ w_hh,
                       const float* __restrict__ b_ih, const float* __restrict__ b_hh,
                       float* __restrict__ Wih, float* __restrict__ Whh, float* __restrict__ bsel)
{
    int i = blockIdx.x * blockDim.x + threadIdx.x;
    if (i >= GSEL * 512) return;
    int r = i >> 9, k = i & 511;
    int orig = ((r >> 9) << 10) + (r & 511);
    Wih[i] = __uint_as_float(f2tf32(w_ih[(long)orig * 512 + k]));
    Whh[i] = __uint_as_float(f2tf32(w_hh[(long)orig * 1024 + k]));
    if (k == 0) bsel[r] = b_ih[orig] + b_hh[orig];
}

// round a weight matrix to tf32 (identity for later fragment loads)
__global__ void k_round(const float* __restrict__ src, float* __restrict__ dst, int n)
{
    int i = blockIdx.x * blockDim.x + threadIdx.x;
    if (i < n) dst[i] = __uint_as_float(f2tf32(src[i]));
}

// ---------------- kernel 2: neighbor encode (sim + exact top-k + mean) ----------------
__global__ void __launch_bounds__(256) k_neighbor(
    const int* __restrict__ query, const int* __restrict__ support,
    const int* __restrict__ qlc, const int* __restrict__ qrc,
    const int* __restrict__ slc, const int* __restrict__ src_,
    const float* __restrict__ emb, float* __restrict__ catmean)
{
    __shared__ int   s_conn[2 * NNB];
    __shared__ float s_center[DD];
    __shared__ float s_sim[NNB];
    __shared__ int   s_sel[NNB];
    __shared__ float s_red[9];

    int tid = threadIdx.x;
    int blk = blockIdx.x;
    const int* conn; int id;
    if (blk < 2 * BB) {
        int b = blk >> 1, s = blk & 1;
        conn = (s ? qrc : qlc) + (long)b * (2 * NNB);
        id = query[2 * b + s];
    } else {
        int t = blk - 2 * BB; int f = t >> 1, s = t & 1;
        conn = (s ? src_ : slc) + (long)f * (2 * NNB);
        id = support[2 * f + s];
    }
    if (tid < 2 * NNB) s_conn[tid] = conn[tid];

    float cv = emb[(long)id * DD + tid];
    s_center[tid] = cv;
    float cs = cv * cv;
    #pragma unroll
    for (int o = 16; o; o >>= 1) cs += __shfl_down_sync(0xffffffffu, cs, o);
    if ((tid & 31) == 0) s_red[tid >> 5] = cs;
    __syncthreads();
    if (tid == 0) { float t = 0.f; for (int i = 0; i < 8; i++) t += s_red[i]; s_red[8] = sqrtf(t); }
    __syncthreads();
    float cnorm = s_red[8];

    int w = tid >> 5, l = tid & 31;
    for (int n = w; n < NNB; n += 8) {
        const float* e = emb + (long)s_conn[2 * n + 1] * DD;
        float d = 0.f, q = 0.f;
        #pragma unroll
        for (int i = l; i < DD; i += 32) { float v = e[i]; d += v * s_center[i]; q += v * v; }
        #pragma unroll
        for (int o = 16; o; o >>= 1) {
            d += __shfl_down_sync(0xffffffffu, d, o);
            q += __shfl_down_sync(0xffffffffu, q, o);
        }
        if (l == 0) s_sim[n] = d / fmaxf(cnorm * sqrtf(q), 1e-8f);
    }
    __syncthreads();

    if (tid < NNB) {
        float sn = s_sim[tid]; int rank = 0;
        #pragma unroll
        for (int m = 0; m < NNB; m++) {
            float sm = s_sim[m];
            rank += (sm > sn) || (sm == sn && m < tid);
        }
        s_sel[tid] = (rank < KK);
    }
    __syncthreads();

    float ra = 0.f, ea = 0.f;
    for (int n = 0; n < NNB; n++) {
        if (s_sel[n]) {
            ra += emb[(long)s_conn[2 * n]     * DD + tid];
            ea += emb[(long)s_conn[2 * n + 1] * DD + tid];
        }
    }
    catmean[(long)blk * 512 + tid]      = ra * (1.0f / KK);
    catmean[(long)blk * 512 + DD + tid] = ea * (1.0f / KK);
}

// ---------------- tf32 mma.sync GEMM, cp.async 4-stage pipeline, 256 threads ----------------
// C = act(A @ W^T + b1 + b2 + R).  A:(M,K) row-major fp32 (rounded at frag load),
// W:(N,K) row-major PRE-ROUNDED tf32 values (raw-bit fragment load).
// N%128==0, K%16==0, M guarded. CTA tile 64x128, 8 warps, warp tile 32x32.
#define SPAD   20       // smem row stride in floats (conflict-free fragment loads)
#define STAGES 4

__device__ __forceinline__ void cp16(uint32_t dst, const void* src, bool valid) {
    asm volatile("cp.async.cg.shared.global [%0], [%1], 16, %2;"
        :: "r"(dst), "l"(src), "r"(valid ? 16u : 0u));
}
#define CP_COMMIT() asm volatile("cp.async.commit_group;" ::: "memory")
#define CP_WAIT2()  asm volatile("cp.async.wait_group 2;" ::: "memory")

__global__ void __launch_bounds__(256, 2) k_gemm_mma(
    const float* __restrict__ A, const float* __restrict__ W,
    const float* __restrict__ b1, const float* __restrict__ b2,
    const float* __restrict__ R, float* __restrict__ C,
    int M, int N, int K, int act)
{
    __shared__ float As[STAGES * 64 * SPAD];
    __shared__ float Bs[STAGES * 128 * SPAD];

    const int tid = threadIdx.x;
    const int wid = tid >> 5, lane = tid & 31;
    const int bn0 = blockIdx.x * 128, bm0 = blockIdx.y * 64;
    const int wm0 = (wid >> 2) * 32;        // warp m offset (0 or 32)
    const int wn0 = (wid & 3) * 32;         // warp n offset (0,32,64,96)
    const int lg = lane >> 2;               // lane group 0..7
    const int lk = lane & 3;                // k-within-4

    // loaders: A -> 1 float4/thread (row = tid/4, col = (tid&3)*4)
    //          B -> 2 float4/thread (row = tid/2, col = (tid&1)*8)
    const int ra = tid >> 2, ca = (tid & 3) * 4;
    const int rb = tid >> 1, cb = (tid & 1) * 8;
    const bool va = (bm0 + ra) < M;
    const float* gA = A + (long)(va ? (bm0 + ra) : 0) * K + ca;
    const float* gB = W + (long)(bn0 + rb) * K + cb;

    const uint32_t sAb = (uint32_t)__cvta_generic_to_shared(As);
    const uint32_t sBb = (uint32_t)__cvta_generic_to_shared(Bs);
    const uint32_t dA = sAb + (uint32_t)(ra * SPAD + ca) * 4u;
    const uint32_t dB = sBb + (uint32_t)(rb * SPAD + cb) * 4u;

    float acc[2][4][4];
    #pragma unroll
    for (int mf = 0; mf < 2; mf++)
        #pragma unroll
        for (int nf = 0; nf < 4; nf++)
            #pragma unroll
            for (int j = 0; j < 4; j++) acc[mf][nf][j] = 0.f;

    const int chunks = K >> 4;

    // prologue: stages 0..2
    #pragma unroll
    for (int s = 0; s < 3; s++) {
        const long kb = (long)s << 4;
        cp16(dA + (uint32_t)(s * 64 * SPAD) * 4u, gA + kb, va);
        uint32_t db = dB + (uint32_t)(s * 128 * SPAD) * 4u;
        cp16(db,      gB + kb,     true);
        cp16(db + 16, gB + kb + 4, true);
        CP_COMMIT();
    }

    for (int kc = 0; kc < chunks; kc++) {
        const int st  = kc & (STAGES - 1);
        const int wst = (kc + 3) & (STAGES - 1);
        CP_WAIT2();
        __syncthreads();

        // issue loads for chunk kc+3 into stage wst
        {
            const int nk = kc + 3;
            if (nk < chunks) {
                const long kb = (long)nk << 4;
                cp16(dA + (uint32_t)(wst * 64 * SPAD) * 4u, gA + kb, va);
                uint32_t db = dB + (uint32_t)(wst * 128 * SPAD) * 4u;
                cp16(db,      gB + kb,     true);
                cp16(db + 16, gB + kb + 4, true);
            }
            CP_COMMIT();
        }

        // compute 2 k8-steps from stage st
        const float* Ast = As + st * 64 * SPAD;
        const float* Bst = Bs + st * 128 * SPAD;
        #pragma unroll
        for (int ks = 0; ks < 2; ks++) {
            const int k0 = ks * 8;
            uint32_t af[2][4];
            #pragma unroll
            for (int mf = 0; mf < 2; mf++) {
                int r0 = wm0 + mf * 16 + lg;
                af[mf][0] = f2tf32(Ast[(r0)     * SPAD + k0 + lk]);
                af[mf][1] = f2tf32(Ast[(r0 + 8) * SPAD + k0 + lk]);
                af[mf][2] = f2tf32(Ast[(r0)     * SPAD + k0 + lk + 4]);
                af[mf][3] = f2tf32(Ast[(r0 + 8) * SPAD + k0 + lk + 4]);
            }
            uint32_t bf[4][2];
            #pragma unroll
            for (int nf = 0; nf < 4; nf++) {
                int n = wn0 + nf * 8 + lg;
                bf[nf][0] = __float_as_uint(Bst[n * SPAD + k0 + lk]);      // pre-rounded
                bf[nf][1] = __float_as_uint(Bst[n * SPAD + k0 + lk + 4]);  // pre-rounded
            }
            #pragma unroll
            for (int mf = 0; mf < 2; mf++)
                #pragma unroll
                for (int nf = 0; nf < 4; nf++) {
                    asm volatile(
                        "mma.sync.aligned.m16n8k8.row.col.f32.tf32.tf32.f32 "
                        "{%0,%1,%2,%3}, {%4,%5,%6,%7}, {%8,%9}, {%0,%1,%2,%3};"
                        : "+f"(acc[mf][nf][0]), "+f"(acc[mf][nf][1]),
                          "+f"(acc[mf][nf][2]), "+f"(acc[mf][nf][3])
                        : "r"(af[mf][0]), "r"(af[mf][1]), "r"(af[mf][2]), "r"(af[mf][3]),
                          "r"(bf[nf][0]), "r"(bf[nf][1]));
                }
        }
    }

    // epilogue: c0:(row,col) c1:(row,col+1) c2:(row+8,col) c3:(row+8,col+1)
    #pragma unroll
    for (int mf = 0; mf < 2; mf++) {
        #pragma unroll
        for (int half = 0; half < 2; half++) {
            int row = bm0 + wm0 + mf * 16 + lg + half * 8;
            if (row >= M) continue;
            #pragma unroll
            for (int nf = 0; nf < 4; nf++) {
                int col = bn0 + wn0 + nf * 8 + lk * 2;
                #pragma unroll
                for (int e = 0; e < 2; e++) {
                    float v = acc[mf][nf][half * 2 + e];
                    int cc = col + e;
                    if (b1) v += b1[cc];
                    if (b2) v += b2[cc];
                    if (R)  v += R[(long)row * N + cc];
                    if (act == 1)      v = fmaxf(v, 0.f);
                    else if (act == 2) v = tanhf(v);
                    C[(long)row * N + cc] = v;
                }
            }
        }
    }
}

// ---------------- layernorm ----------------
__global__ void k_layernorm(const float* __restrict__ X, const float* __restrict__ g,
                            const float* __restrict__ b, float* __restrict__ Y)
{
    __shared__ float rs[8], rq[8];
    int r = blockIdx.x, t = threadIdx.x;
    const float* x = X + (long)r * 512;
    float v0 = x[t], v1 = x[t + 256];
    float s = v0 + v1, q = v0 * v0 + v1 * v1;
    #pragma unroll
    for (int o = 16; o; o >>= 1) {
        s += __shfl_down_sync(0xffffffffu, s, o);
        q += __shfl_down_sync(0xffffffffu, q, o);
    }
    if ((t & 31) == 0) { rs[t >> 5] = s; rq[t >> 5] = q; }
    __syncthreads();
    if (t == 0) {
        float ts = 0.f, tq = 0.f;
        for (int i = 0; i < 8; i++) { ts += rs[i]; tq += rq[i]; }
        rs[0] = ts; rq[0] = tq;
    }
    __syncthreads();
    float m   = rs[0] * (1.f / 512.f);
    float var = rq[0] * (1.f / 512.f) - m * m;
    float inv = 1.0f / sqrtf(var + 1e-5f);
    Y[(long)r * 512 + t]       = (v0 - m) * inv * g[t]       + b[t];
    Y[(long)r * 512 + t + 256] = (v1 - m) * inv * g[t + 256] + b[t + 256];
}

__global__ void k_sgmean(const float* __restrict__ enc, float* __restrict__ sg)
{
    int t = threadIdx.x;
    float a = 0.f;
    for (int f = 0; f < FF; f++) a += enc[(long)(BB + f) * 512 + t];
    sg[t] = a * (1.0f / FF);
}

__global__ void k_svec(const float* __restrict__ w_hh, const float* __restrict__ sg,
                       float* __restrict__ S)
{
    int gw = (blockIdx.x * blockDim.x + threadIdx.x) >> 5;
    int l  = threadIdx.x & 31;
    if (gw >= GSEL) return;
    int orig = ((gw >> 9) << 10) + (gw & 511);
    const float* row = w_hh + (long)orig * 1024 + 512;
    float a = 0.f;
    for (int j = l; j < 512; j += 32) a += row[j] * sg[j];
    #pragma unroll
    for (int o = 16; o; o >>= 1) a += __shfl_down_sync(0xffffffffu, a, o);
    if (l == 0) S[gw] = a;
}

__global__ void k_lstm(const float* __restrict__ gates, const float* __restrict__ qg,
                       float* __restrict__ c, float* __restrict__ h, int first)
{
    int i = blockIdx.x * blockDim.x + threadIdx.x;
    if (i >= BB * 512) return;
    int b = i >> 9, j = i & 511;
    const float* gr = gates + (long)b * GSEL;
    float gi = gr[j], gf = gr[j + 512], gg = gr[j + 1024], go = gr[j + 1536];
    float cp = first ? 0.f : c[i];
    float cn = (1.f / (1.f + expf(-gf))) * cp + (1.f / (1.f + expf(-gi))) * tanhf(gg);
    c[i] = cn;
    h[i] = qg[i] + (1.f / (1.f + expf(-go))) * tanhf(cn);
}

__global__ void k_sgnorm(const float* __restrict__ sg, float* __restrict__ sgn)
{
    __shared__ float red[16];
    int t = threadIdx.x;
    float v = sg[t], q = v * v;
    #pragma unroll
    for (int o = 16; o; o >>= 1) q += __shfl_down_sync(0xffffffffu, q, o);
    if ((t & 31) == 0) red[t >> 5] = q;
    __syncthreads();
    if (t == 0) { float s = 0.f; for (int i = 0; i < 16; i++) s += red[i]; red[0] = sqrtf(s); }
    __syncthreads();
    sgn[t] = v / fmaxf(red[0], 1e-12f);
}

__global__ void k_final(const float* __restrict__ h, const float* __restrict__ sgn,
                        float* __restrict__ out)
{
    int gw = (blockIdx.x * blockDim.x + threadIdx.x) >> 5;
    int l  = threadIdx.x & 31;
    if (gw >= BB) return;
    const float* hr = h + (long)gw * 512;
    float d = 0.f, q = 0.f;
    for (int j = l; j < 512; j += 32) { float v = hr[j]; d += v * sgn[j]; q += v * v; }
    #pragma unroll
    for (int o = 16; o; o >>= 1) {
        d += __shfl_down_sync(0xffffffffu, d, o);
        q += __shfl_down_sync(0xffffffffu, q, o);
    }
    if (l == 0) out[gw] = d / fmaxf(sqrtf(q), 1e-12f);
}

// ---------------- launch ----------------
extern "C" void kernel_launch(void* const* d_in, const int* in_sizes, int n_in,
                              void* d_out, int out_size)
{
    const int*   query   = (const int*)  d_in[0];
    const int*   support = (const int*)  d_in[1];
    const int*   qlc     = (const int*)  d_in[2];
    const int*   qrc     = (const int*)  d_in[4];
    const int*   slc     = (const int*)  d_in[6];
    const int*   src_    = (const int*)  d_in[8];
    const float* emb     = (const float*)d_in[10];
    const float* gcn_w   = (const float*)d_in[11];
    const float* gcn_wb  = (const float*)d_in[12];
    const float* gcn_b   = (const float*)d_in[13];
    const float* p1_w    = (const float*)d_in[14];
    const float* p1_b    = (const float*)d_in[15];
    const float* p2_w    = (const float*)d_in[16];
    const float* p2_b    = (const float*)d_in[17];
    const float* ln_g    = (const float*)d_in[18];
    const float* ln_b    = (const float*)d_in[19];
    const float* w_ih    = (const float*)d_in[20];
    const float* w_hh    = (const float*)d_in[21];
    const float* b_ih    = (const float*)d_in[22];
    const float* b_hh    = (const float*)d_in[23];
    float* out = (float*)d_out;

    float *catmean, *x, *h1, *o, *enc, *sg, *sgn, *Wih, *Whh, *bsel, *Svec, *G0, *gates, *c, *hcur;
    float *gcnw, *p1w, *p2w;
    cudaGetSymbolAddress((void**)&catmean, g_catmean);
    cudaGetSymbolAddress((void**)&x,       g_x);
    cudaGetSymbolAddress((void**)&h1,      g_h1);
    cudaGetSymbolAddress((void**)&o,       g_o);
    cudaGetSymbolAddress((void**)&enc,     g_enc);
    cudaGetSymbolAddress((void**)&sg,      g_sg);
    cudaGetSymbolAddress((void**)&sgn,     g_sgn);
    cudaGetSymbolAddress((void**)&Wih,     g_Wih);
    cudaGetSymbolAddress((void**)&Whh,     g_Whh);
    cudaGetSymbolAddress((void**)&bsel,    g_bsel);
    cudaGetSymbolAddress((void**)&Svec,    g_Svec);
    cudaGetSymbolAddress((void**)&G0,      g_G0);
    cudaGetSymbolAddress((void**)&gates,   g_gates);
    cudaGetSymbolAddress((void**)&c,       g_c);
    cudaGetSymbolAddress((void**)&hcur,    g_hcur);
    cudaGetSymbolAddress((void**)&gcnw,    g_gcnw);
    cudaGetSymbolAddress((void**)&p1w,     g_p1w);
    cudaGetSymbolAddress((void**)&p2w,     g_p2w);

    // 1. weight prep: selected-gate copy (rounded) + tf32 rounding of MLP weights
    k_prep<<<(GSEL * 512) / 512, 512>>>(w_ih, w_hh, b_ih, b_hh, Wih, Whh, bsel);
    k_round<<<(256 * 512) / 512, 512>>>(gcn_w, gcnw, 256 * 512);
    k_round<<<(1024 * 512) / 512, 512>>>(p1_w, p1w, 1024 * 512);
    k_round<<<(512 * 1024) / 512, 512>>>(p2_w, p2w, 512 * 1024);

    // 2. neighbor encoder gather + top-k + mean -> catmean (4106 x 512)
    k_neighbor<<<MCM, 256>>>(query, support, qlc, qrc, slc, src_, emb, catmean);

    // 3. GCN: tanh(catmean @ gcn_w^T + wb + b) -> x (reshaped 2053 x 512)
    k_gemm_mma<<<dim3(2, 65), 256>>>(catmean, gcnw, gcn_wb, gcn_b, nullptr, x, MCM, 256, 512, 2);

    // 4. support encoder MLP + LN
    k_gemm_mma<<<dim3(8, 33), 256>>>(x,  p1w, p1_b, nullptr, nullptr, h1, MX, 1024, 512, 1);
    k_gemm_mma<<<dim3(4, 33), 256>>>(h1, p2w, p2_b, nullptr, x,       o,  MX, 512, 1024, 0);
    k_layernorm<<<MX, 256>>>(o, ln_g, ln_b, enc);
    k_sgmean<<<1, 512>>>(enc, sg);

    // 5. G0 = query_g @ Wih_sel^T + (b_ih + b_hh)_sel
    k_gemm_mma<<<dim3(16, 32), 256>>>(enc, Wih, bsel, nullptr, nullptr, G0, BB, GSEL, 512, 0);
    k_svec<<<(GSEL * 32) / 256, 256>>>(w_hh, sg, Svec);

    // 6. LSTM steps
    k_lstm<<<(BB * 512) / 256, 256>>>(G0, enc, c, hcur, 1);
    for (int s = 1; s < 4; s++) {
        k_gemm_mma<<<dim3(16, 32), 256>>>(hcur, Whh, Svec, nullptr, G0, gates, BB, GSEL, 512, 0);
        k_lstm<<<(BB * 512) / 256, 256>>>(gates, enc, c, hcur, 0);
    }

    // 7. cosine output
    k_sgnorm<<<1, 512>>>(sg, sgn);
    k_final<<<(BB * 32) / 256, 256>>>(hcur, sgn, out);
}